// round 1
// baseline (speedup 1.0000x reference)
#include <cuda_runtime.h>
#include <math.h>

// Problem constants (fixed by setup_inputs)
#define Bd   8
#define Pd   5
#define Qd   75
#define Cd   640
#define HWd  49
#define BQd  (Bd*Qd)          // 600
#define NMAT (Bd*Qd*Pd)       // 3000
#define IMG  (Cd*HWd)         // 31360
#define TEMPER  12.5f
#define INV_EPS 20.0f         // 1/0.05
#define S_ITERS 100

// ---------------- scratch (device globals; no allocation) ----------------
__device__ float g_supn[Bd*Pd*IMG];     // normalized support features [b,p,c,hw]
__device__ float g_qryn[Bd*Qd*IMG];     // normalized query features   [b,q,c,hw]
__device__ float g_sgap[Bd*Pd*Cd];      // support GAP [b,p,c]
__device__ float g_qgap[Bd*Qd*Cd];      // query GAP   [b,q,c]
__device__ float g_ma[NMAT*HWd];        // row marginals a [b,q,p,hw]
__device__ float g_mb[NMAT*HWd];        // col marginals b [b,q,p,hw]
__device__ float g_logits[NMAT];        // logits [b,q,p]

// ---------------- kernel 1: per-image channel-normalize + GAP ------------
// One block per image. Stage image in dynamic SMEM (coalesced), then:
//   cmean[m]  = mean_c x[c,m] ; rnorm[m] = 1/max(||x[:,m]-mean||, 1e-8)
//   gap[c]    = mean_m x[c,m]
//   xn[c,m]   = (x[c,m]-cmean[m])*rnorm[m]
extern __shared__ float sh_dyn[];
__global__ void prep_kernel(const float* __restrict__ x,
                            float* __restrict__ xn,
                            float* __restrict__ gap) {
    float* img   = sh_dyn;            // IMG
    float* cmean = sh_dyn + IMG;      // HW
    float* crn   = cmean + HWd;       // HW

    const int t = threadIdx.x;
    const long base = (long)blockIdx.x * IMG;

    // coalesced staging (float4)
    const float4* src4 = (const float4*)(x + base);
    float4* dst4 = (float4*)img;
    for (int i = t; i < IMG/4; i += blockDim.x) dst4[i] = src4[i];
    __syncthreads();

    // per-column (hw) stats; warp per column, strided LDS (stride 49 -> conflict-free)
    const int w = t >> 5, lane = t & 31;
    for (int m = w; m < HWd; m += 8) {
        float s = 0.f;
        for (int c = lane; c < Cd; c += 32) s += img[c*HWd + m];
        #pragma unroll
        for (int o = 16; o; o >>= 1) s += __shfl_xor_sync(0xffffffffu, s, o);
        float mean = s * (1.0f/Cd);
        float ss = 0.f;
        for (int c = lane; c < Cd; c += 32) { float d = img[c*HWd + m] - mean; ss += d*d; }
        #pragma unroll
        for (int o = 16; o; o >>= 1) ss += __shfl_xor_sync(0xffffffffu, ss, o);
        if (lane == 0) {
            cmean[m] = mean;
            crn[m]   = 1.0f / fmaxf(sqrtf(ss), 1e-8f);
        }
    }
    __syncthreads();

    // GAP over hw of RAW features
    for (int c = t; c < Cd; c += blockDim.x) {
        float g = 0.f;
        #pragma unroll 7
        for (int m = 0; m < HWd; m++) g += img[c*HWd + m];
        gap[(long)blockIdx.x*Cd + c] = g * (1.0f/HWd);
    }

    // normalized write-back (coalesced)
    for (int i = t; i < IMG; i += blockDim.x) {
        int m = i - (i / HWd) * HWd;
        xn[base + i] = (img[i] - cmean[m]) * crn[m];
    }
}

// ---------------- kernel 2: marginals a,b per (b,q,p) --------------------
// One block per (b,q). Computes
//   w1[p,m] = relu(sum_c qry_raw[b,q,c,m] * sgap[b,p,c]) + 1e-3 + 1e-5
//   w2[p,n] = relu(sum_c sup_raw[b,p,c,n] * qgap[b,q,c]) + 1e-3 + 1e-5
// then normalizes each 49-vector to a probability.
__global__ void marg_kernel(const float* __restrict__ supp,
                            const float* __restrict__ qry) {
    __shared__ float sg[Pd*Cd];     // 12.8 KB
    __shared__ float qg[Cd];
    __shared__ float wa[Pd*HWd], wb[Pd*HWd];
    __shared__ float suma[Pd], sumb[Pd];

    const int t = threadIdx.x;
    const int bq = blockIdx.x;
    const int b  = bq / Qd;

    for (int i = t; i < Pd*Cd; i += blockDim.x) sg[i] = g_sgap[(long)b*Pd*Cd + i];
    for (int i = t; i < Cd;    i += blockDim.x) qg[i] = g_qgap[(long)bq*Cd + i];
    __syncthreads();

    if (t < Pd*HWd) {
        const int p = t / HWd, m = t - p*HWd;
        const float* qptr = qry + (long)bq*IMG + m;
        const float* sgp  = sg + p*Cd;
        float acc = 0.f;
        #pragma unroll 4
        for (int c = 0; c < Cd; c++) acc += qptr[(long)c*HWd] * sgp[c];
        wa[t] = (fmaxf(acc, 0.f) + 1e-3f) + 1e-5f;

        const float* sptr = supp + (long)(b*Pd + p)*IMG + m;
        float acc2 = 0.f;
        #pragma unroll 4
        for (int c = 0; c < Cd; c++) acc2 += sptr[(long)c*HWd] * qg[c];
        wb[t] = (fmaxf(acc2, 0.f) + 1e-3f) + 1e-5f;
    }
    __syncthreads();
    if (t < Pd) {
        float s = 0.f, s2 = 0.f;
        for (int m = 0; m < HWd; m++) { s += wa[t*HWd + m]; s2 += wb[t*HWd + m]; }
        suma[t] = 1.0f / s; sumb[t] = 1.0f / s2;
    }
    __syncthreads();
    if (t < Pd*HWd) {
        const int p = t / HWd;
        g_ma[(long)bq*Pd*HWd + t] = wa[t] * suma[p];
        g_mb[(long)bq*Pd*HWd + t] = wb[t] * sumb[p];
    }
}

// ---------------- kernel 3: fused S-GEMM + linear Sinkhorn + logits ------
// One block per (b,q,p). 256 threads.
//  Phase A: S[49,49] = sum_c qryn[c,:]^T supn[c,:]  (4x4 register-tiled, 13x13 threads)
//  Phase B: K = exp((S - Smax)/eps)  (shift-invariant transport plan)
//  Phase C: linear Sinkhorn: u = a/(Kv); v = b/(K^T u); K rows/cols cached in regs
//  Phase D: logits = TEMPER * sum S .* (u K v)
__global__ void __launch_bounds__(256)
emd_kernel() {
    __shared__ __align__(16) float qch[32*52];
    __shared__ __align__(16) float sch[32*52];
    __shared__ float Ssh[HWd*HWd];
    __shared__ float Ksh[HWd*HWd];
    __shared__ float ash[HWd], bsh[HWd], ush[HWd], vsh[HWd];
    __shared__ float red[33];

    const int t   = threadIdx.x;
    const int idx = blockIdx.x;
    const int p   = idx % Pd;
    const int bq  = idx / Pd;
    const int b   = bq / Qd;
    const long qbase = (long)bq * IMG;
    const long sbase = (long)(b*Pd + p) * IMG;

    // zero SMEM chunk buffers (pad columns 49..51 stay zero forever)
    for (int i = t; i < 32*52; i += 256) { qch[i] = 0.f; sch[i] = 0.f; }

    float acc[4][4];
    #pragma unroll
    for (int i = 0; i < 4; i++)
        #pragma unroll
        for (int j = 0; j < 4; j++) acc[i][j] = 0.f;

    const int tx = t % 13, ty = t / 13;     // valid for t<169
    const bool act = (t < 169);
    const int tm = tx*4, tn = ty*4;
    __syncthreads();

    // --- Phase A: GEMM over c in 20 chunks of 32 ---
    for (int ch = 0; ch < 20; ch++) {
        for (int i = t; i < 32*HWd; i += 256) {
            int r = i / HWd, cc = i - r*HWd;
            qch[r*52 + cc] = g_qryn[qbase + (long)ch*(32*HWd) + i];
            sch[r*52 + cc] = g_supn[sbase + (long)ch*(32*HWd) + i];
        }
        __syncthreads();
        if (act) {
            #pragma unroll 4
            for (int c = 0; c < 32; c++) {
                float4 qv = *(const float4*)&qch[c*52 + tm];
                float4 sv = *(const float4*)&sch[c*52 + tn];
                float qa[4] = {qv.x, qv.y, qv.z, qv.w};
                float sa[4] = {sv.x, sv.y, sv.z, sv.w};
                #pragma unroll
                for (int i = 0; i < 4; i++)
                    #pragma unroll
                    for (int j = 0; j < 4; j++) acc[i][j] += qa[i] * sa[j];
            }
        }
        __syncthreads();
    }

    // write S + block max(S)
    float lmax = -1e30f;
    if (act) {
        #pragma unroll
        for (int i = 0; i < 4; i++)
            #pragma unroll
            for (int j = 0; j < 4; j++) {
                int r = tm + i, cn = tn + j;
                if (r < HWd && cn < HWd) {
                    Ssh[r*HWd + cn] = acc[i][j];
                    lmax = fmaxf(lmax, acc[i][j]);
                }
            }
    }
    #pragma unroll
    for (int o = 16; o; o >>= 1) lmax = fmaxf(lmax, __shfl_xor_sync(0xffffffffu, lmax, o));
    if ((t & 31) == 0) red[t >> 5] = lmax;
    __syncthreads();
    if (t < 32) {
        float v = (t < 8) ? red[t] : -1e30f;
        #pragma unroll
        for (int o = 4; o; o >>= 1) v = fmaxf(v, __shfl_xor_sync(0xffffffffu, v, o));
        if (t == 0) red[32] = v;
    }
    __syncthreads();
    const float Smax = red[32];

    // --- Phase B: K = exp((S - Smax)/eps); marginals; v init ---
    for (int e = t; e < HWd*HWd; e += 256)
        Ksh[e] = __expf((Ssh[e] - Smax) * INV_EPS);
    if (t < HWd) {
        ash[t] = g_ma[(long)idx*HWd + t];
        bsh[t] = g_mb[(long)idx*HWd + t];
        vsh[t] = 1.0f;
    }
    __syncthreads();

    // --- Phase C: linear Sinkhorn with register-cached K rows/cols ---
    const bool isrow = (t < 49);
    const bool iscol = (t >= 64 && t < 113);
    float Kreg[49];
    if (isrow) {
        #pragma unroll
        for (int k = 0; k < 49; k++) Kreg[k] = Ksh[t*49 + k];
    }
    if (iscol) {
        const int n = t - 64;
        #pragma unroll
        for (int k = 0; k < 49; k++) Kreg[k] = Ksh[k*49 + n];
    }
    const float am = isrow ? ash[t] : 0.f;
    const float bn = iscol ? bsh[t-64] : 0.f;

    for (int it = 0; it < S_ITERS; it++) {
        if (isrow) {
            float d0=0.f, d1=0.f, d2=0.f, d3=0.f;
            #pragma unroll
            for (int k = 0; k < 12; k++) {
                d0 += Kreg[4*k+0] * vsh[4*k+0];
                d1 += Kreg[4*k+1] * vsh[4*k+1];
                d2 += Kreg[4*k+2] * vsh[4*k+2];
                d3 += Kreg[4*k+3] * vsh[4*k+3];
            }
            d0 += Kreg[48] * vsh[48];
            ush[t] = am / ((d0 + d1) + (d2 + d3));
        }
        __syncthreads();
        if (iscol) {
            float d0=0.f, d1=0.f, d2=0.f, d3=0.f;
            #pragma unroll
            for (int k = 0; k < 12; k++) {
                d0 += Kreg[4*k+0] * ush[4*k+0];
                d1 += Kreg[4*k+1] * ush[4*k+1];
                d2 += Kreg[4*k+2] * ush[4*k+2];
                d3 += Kreg[4*k+3] * ush[4*k+3];
            }
            d0 += Kreg[48] * ush[48];
            vsh[t-64] = bn / ((d0 + d1) + (d2 + d3));
        }
        __syncthreads();
    }

    // --- Phase D: logits = TEMPER * sum S .* (u K v) ---
    float part = 0.f;
    for (int e = t; e < HWd*HWd; e += 256) {
        int m = e / HWd, n = e - m*HWd;
        part += Ssh[e] * Ksh[e] * ush[m] * vsh[n];
    }
    #pragma unroll
    for (int o = 16; o; o >>= 1) part += __shfl_xor_sync(0xffffffffu, part, o);
    if ((t & 31) == 0) red[t >> 5] = part;
    __syncthreads();
    if (t == 0) {
        float s = 0.f;
        #pragma unroll
        for (int i = 0; i < 8; i++) s += red[i];
        g_logits[idx] = TEMPER * s;
    }
}

// ---------------- kernel 4: cross-entropy loss ----------------------------
__global__ void loss_kernel(const int* __restrict__ qy, float* __restrict__ out) {
    __shared__ float red[8];
    const int t = threadIdx.x;
    float s = 0.f;
    for (int r = t; r < BQd; r += 256) {
        float l[Pd];
        #pragma unroll
        for (int k = 0; k < Pd; k++) l[k] = g_logits[r*Pd + k];
        float mx = l[0];
        #pragma unroll
        for (int k = 1; k < Pd; k++) mx = fmaxf(mx, l[k]);
        float se = 0.f;
        #pragma unroll
        for (int k = 0; k < Pd; k++) se += expf(l[k] - mx);
        float lse = mx + logf(se);
        int y = qy[r];
        s += lse - l[y];
    }
    #pragma unroll
    for (int o = 16; o; o >>= 1) s += __shfl_xor_sync(0xffffffffu, s, o);
    if ((t & 31) == 0) red[t >> 5] = s;
    __syncthreads();
    if (t == 0) {
        float tot = 0.f;
        #pragma unroll
        for (int i = 0; i < 8; i++) tot += red[i];
        out[0] = tot * (1.0f / BQd);
    }
}

// ---------------- launch ---------------------------------------------------
extern "C" void kernel_launch(void* const* d_in, const int* in_sizes, int n_in,
                              void* d_out, int out_size) {
    const float* sup = (const float*)d_in[0];
    const float* qry = (const float*)d_in[1];
    const int*   qy  = (const int*)d_in[3];
    float* out = (float*)d_out;

    float *supn, *qryn, *sgap, *qgap;
    cudaGetSymbolAddress((void**)&supn, g_supn);
    cudaGetSymbolAddress((void**)&qryn, g_qryn);
    cudaGetSymbolAddress((void**)&sgap, g_sgap);
    cudaGetSymbolAddress((void**)&qgap, g_qgap);

    const int prep_smem = (IMG + 2*HWd) * (int)sizeof(float);
    cudaFuncSetAttribute(prep_kernel, cudaFuncAttributeMaxDynamicSharedMemorySize, prep_smem);

    prep_kernel<<<Bd*Pd, 256, prep_smem>>>(sup, supn, sgap);
    prep_kernel<<<Bd*Qd, 256, prep_smem>>>(qry, qryn, qgap);
    marg_kernel<<<BQd, 256>>>(sup, qry);
    emd_kernel<<<NMAT, 256>>>();
    loss_kernel<<<1, 256>>>(qy, out);
}

// round 2
// speedup vs baseline: 1.5286x; 1.5286x over previous
#include <cuda_runtime.h>
#include <math.h>

// Problem constants (fixed by setup_inputs)
#define Bd   8
#define Pd   5
#define Qd   75
#define Cd   640
#define HWd  49
#define BQd  (Bd*Qd)          // 600
#define NMAT (Bd*Qd*Pd)       // 3000
#define IMG  (Cd*HWd)         // 31360
#define QSTRIDE 52            // padded m-stride for qryn
#define SSTRIDE 248           // 5*49 + 3 pad for supn
#define SMATS   2404          // padded per-matrix stride for g_S (16B-divisible)
#define TEMPER  12.5f
#define INV_EPS 20.0f
#define S_ITERS 100

// ---------------- scratch (device globals; no allocation) ----------------
__device__ float g_supn[Bd*Cd*SSTRIDE];     // normalized support [b][c][p*49+n], pads 0
__device__ float g_qryn[(size_t)BQd*Cd*QSTRIDE]; // normalized query [bq][c][m], pads 0
__device__ float g_sgap[Bd*Pd*Cd];          // support GAP [b,p,c]
__device__ float g_qgap[BQd*Cd];            // query GAP [bq,c]
__device__ float g_ma[NMAT*HWd];            // row marginals (prob)
__device__ float g_mb[NMAT*HWd];            // col marginals (prob)
__device__ float g_S[(size_t)NMAT*SMATS];   // similarity matrices
__device__ float g_Smax[NMAT];              // per-matrix max(S)
__device__ float g_logits[NMAT];

// ---------------- helpers ----------------
__device__ __forceinline__ float2 ffma2(float2 a, float2 b, float2 c) {
    float2 d;
    asm("fma.rn.f32x2 %0, %1, %2, %3;"
        : "=l"(reinterpret_cast<unsigned long long&>(d))
        : "l"(reinterpret_cast<unsigned long long&>(a)),
          "l"(reinterpret_cast<unsigned long long&>(b)),
          "l"(reinterpret_cast<unsigned long long&>(c)));
    return d;
}
__device__ __forceinline__ unsigned ordf(float f) {
    unsigned u = __float_as_uint(f);
    return (u & 0x80000000u) ? ~u : (u | 0x80000000u);
}
__device__ __forceinline__ float unordf(unsigned u) {
    return (u & 0x80000000u) ? __uint_as_float(u & 0x7fffffffu) : __uint_as_float(~u);
}

// ---------------- kernel 1a: support prep ----------------
// grid 40 = (b,p). Normalize channels, GAP, write padded supn layout.
extern __shared__ float sh_dyn[];
__global__ void prep_sup(const float* __restrict__ x) {
    float* img   = sh_dyn;          // IMG (raw)
    float* cmean = sh_dyn + IMG;    // HW
    float* crn   = cmean + HWd;     // HW
    const int t = threadIdx.x;
    const int bp = blockIdx.x, b = bp / Pd, p = bp % Pd;

    const float4* src = (const float4*)(x + (size_t)bp*IMG);
    float4* dst = (float4*)img;
    for (int i = t; i < IMG/4; i += 512) dst[i] = src[i];
    __syncthreads();

    const int w = t >> 5, lane = t & 31;
    for (int m = w; m < HWd; m += 16) {
        float s = 0.f;
        for (int c = lane; c < Cd; c += 32) s += img[c*HWd + m];
        #pragma unroll
        for (int o = 16; o; o >>= 1) s += __shfl_xor_sync(0xffffffffu, s, o);
        float mean = s * (1.0f/Cd);
        float ss = 0.f;
        for (int c = lane; c < Cd; c += 32) { float d = img[c*HWd + m] - mean; ss += d*d; }
        #pragma unroll
        for (int o = 16; o; o >>= 1) ss += __shfl_xor_sync(0xffffffffu, ss, o);
        if (lane == 0) { cmean[m] = mean; crn[m] = 1.0f / fmaxf(sqrtf(ss), 1e-8f); }
    }
    __syncthreads();

    for (int c = t; c < Cd; c += 512) {
        float g = 0.f;
        #pragma unroll 7
        for (int m = 0; m < HWd; m++) g += img[c*HWd + m];
        g_sgap[(size_t)bp*Cd + c] = g * (1.0f/HWd);
    }
    for (int i = t; i < IMG; i += 512) {
        int c = i / HWd, n = i - c*HWd;
        g_supn[((size_t)b*Cd + c)*SSTRIDE + p*HWd + n] = (img[i] - cmean[n]) * crn[n];
    }
    if (p == 0) {
        for (int i = t; i < Cd*3; i += 512) {
            int c = i / 3, k = i - c*3;
            g_supn[((size_t)b*Cd + c)*SSTRIDE + Pd*HWd + k] = 0.f;
        }
    }
}

// ---------------- kernel 1b: query prep + w1 marginals ----------------
// grid 600 = (b,q). Normalize, GAP, padded write, and w1 = relu(qry_raw . sgap).
__global__ void prep_qry(const float* __restrict__ x) {
    float* img   = sh_dyn;               // IMG (raw)
    float* cmean = sh_dyn + IMG;         // HW
    float* crn   = cmean + HWd;          // HW
    float* sgb   = crn + HWd;            // Pd*Cd
    float* wa    = sgb + Pd*Cd;          // 245
    float* rs    = wa + Pd*HWd;          // 5
    const int t = threadIdx.x;
    const int bq = blockIdx.x, b = bq / Qd;

    const float4* src = (const float4*)(x + (size_t)bq*IMG);
    float4* dst = (float4*)img;
    for (int i = t; i < IMG/4; i += 512) dst[i] = src[i];
    for (int i = t; i < Pd*Cd; i += 512) sgb[i] = g_sgap[(size_t)b*Pd*Cd + i];
    __syncthreads();

    const int w = t >> 5, lane = t & 31;
    for (int m = w; m < HWd; m += 16) {
        float s = 0.f;
        for (int c = lane; c < Cd; c += 32) s += img[c*HWd + m];
        #pragma unroll
        for (int o = 16; o; o >>= 1) s += __shfl_xor_sync(0xffffffffu, s, o);
        float mean = s * (1.0f/Cd);
        float ss = 0.f;
        for (int c = lane; c < Cd; c += 32) { float d = img[c*HWd + m] - mean; ss += d*d; }
        #pragma unroll
        for (int o = 16; o; o >>= 1) ss += __shfl_xor_sync(0xffffffffu, ss, o);
        if (lane == 0) { cmean[m] = mean; crn[m] = 1.0f / fmaxf(sqrtf(ss), 1e-8f); }
    }

    // GAP (raw)
    for (int c = t; c < Cd; c += 512) {
        float g = 0.f;
        #pragma unroll 7
        for (int m = 0; m < HWd; m++) g += img[c*HWd + m];
        g_qgap[(size_t)bq*Cd + c] = g * (1.0f/HWd);
    }

    // w1[p,m] = relu(sum_c img[c,m]*sgap[p,c]) + 1e-3 + 1e-5
    if (t < Pd*HWd) {
        const int p = t / HWd, m = t - p*HWd;
        const float* sgp = sgb + p*Cd;
        float acc = 0.f;
        #pragma unroll 4
        for (int c = 0; c < Cd; c++) acc += img[c*HWd + m] * sgp[c];
        wa[t] = (fmaxf(acc, 0.f) + 1e-3f) + 1e-5f;
    }
    __syncthreads();
    if (t < Pd) {
        float s = 0.f;
        for (int m = 0; m < HWd; m++) s += wa[t*HWd + m];
        rs[t] = 1.0f / s;
    }
    __syncthreads();
    if (t < Pd*HWd) {
        const int p = t / HWd;
        g_ma[((size_t)bq*Pd + p)*HWd + (t - p*HWd)] = wa[t] * rs[p];
    }

    // normalized padded write-back
    for (int i = t; i < Cd*QSTRIDE; i += 512) {
        int c = i / QSTRIDE, m = i - c*QSTRIDE;
        float v = 0.f;
        if (m < HWd) v = (img[c*HWd + m] - cmean[m]) * crn[m];
        g_qryn[(size_t)bq*Cd*QSTRIDE + i] = v;
    }
}

// ---------------- kernel 2: w2 marginals ----------------
// grid 40 = (b,p): w2[q,n] = relu(sum_c sup_raw[c,n] * qgap[q,c]) for all 75 q.
__global__ void __launch_bounds__(256) w2_kernel(const float* __restrict__ sup) {
    __shared__ float sch[32*HWd];       // chunk [32c][49n]
    __shared__ float gch[Qd*32];        // chunk [75q][32c]
    __shared__ float wb[Qd*HWd];        // 75*49
    __shared__ float rsum[Qd];
    const int t = threadIdx.x;
    const int bp = blockIdx.x, b = bp / Pd, p = bp % Pd;
    const bool act = t < Pd*HWd;        // 245
    const int n = t % HWd, qg = t / HWd; // qg in 0..4 (for act)

    float acc[15];
    #pragma unroll
    for (int j = 0; j < 15; j++) acc[j] = 0.f;

    for (int ch = 0; ch < 20; ch++) {
        for (int i = t; i < 32*HWd; i += 256)
            sch[i] = sup[(size_t)bp*IMG + ch*(32*HWd) + i];
        for (int i = t; i < Qd*32; i += 256) {
            int q = i / 32, cc = i - q*32;
            gch[i] = g_qgap[((size_t)b*Qd + q)*Cd + ch*32 + cc];
        }
        __syncthreads();
        if (act) {
            #pragma unroll 4
            for (int cc = 0; cc < 32; cc++) {
                float s = sch[cc*HWd + n];
                #pragma unroll
                for (int j = 0; j < 15; j++)
                    acc[j] += s * gch[(qg*15 + j)*32 + cc];
            }
        }
        __syncthreads();
    }
    if (act) {
        #pragma unroll
        for (int j = 0; j < 15; j++)
            wb[(qg*15 + j)*HWd + n] = (fmaxf(acc[j], 0.f) + 1e-3f) + 1e-5f;
    }
    __syncthreads();
    if (t < Qd) {
        float s = 0.f;
        for (int k = 0; k < HWd; k++) s += wb[t*HWd + k];
        rsum[t] = 1.0f / s;
    }
    __syncthreads();
    if (act) {
        #pragma unroll
        for (int j = 0; j < 15; j++) {
            int q = qg*15 + j;
            g_mb[(((size_t)b*Qd + q)*Pd + p)*HWd + n] = wb[q*HWd + n] * rsum[q];
        }
    }
}

// ---------------- kernel 3: batched S GEMM ----------------
// grid 600 = (b,q): S[5,49,49] = qryn^T @ supn. 8x8 tiles, f32x2 packed FMA.
__global__ void __launch_bounds__(256) sgemm_kernel() {
    __shared__ __align__(16) float qch[32*QSTRIDE];   // 6.5 KB
    __shared__ __align__(16) float sch[32*SSTRIDE];   // 31.7 KB
    __shared__ unsigned smaxs[Pd];
    const int t = threadIdx.x;
    const int bq = blockIdx.x, b = bq / Qd;
    if (t < Pd) smaxs[t] = 0u;

    const int tx = t % 7, ty = t / 7;
    const bool act = t < 217;
    const int tm = tx*8, tn = ty*8;

    float2 acc[8][4];
    #pragma unroll
    for (int i = 0; i < 8; i++)
        #pragma unroll
        for (int j = 0; j < 4; j++) acc[i][j] = make_float2(0.f, 0.f);

    const float4* qg = (const float4*)(g_qryn + (size_t)bq*Cd*QSTRIDE);
    const float4* sg = (const float4*)(g_supn + (size_t)b*Cd*SSTRIDE);

    #pragma unroll 1
    for (int ch = 0; ch < 20; ch++) {
        for (int i = t; i < 32*QSTRIDE/4; i += 256) ((float4*)qch)[i] = qg[ch*(32*QSTRIDE/4) + i];
        for (int i = t; i < 32*SSTRIDE/4; i += 256) ((float4*)sch)[i] = sg[ch*(32*SSTRIDE/4) + i];
        __syncthreads();
        if (act) {
            #pragma unroll 8
            for (int c = 0; c < 32; c++) {
                float4 q0 = *(const float4*)&qch[c*QSTRIDE + tm];
                float4 q1 = *(const float4*)&qch[c*QSTRIDE + tm + 4];
                float4 s0 = *(const float4*)&sch[c*SSTRIDE + tn];
                float4 s1 = *(const float4*)&sch[c*SSTRIDE + tn + 4];
                float qa[8] = {q0.x,q0.y,q0.z,q0.w,q1.x,q1.y,q1.z,q1.w};
                float2 sb[4] = {make_float2(s0.x,s0.y), make_float2(s0.z,s0.w),
                                make_float2(s1.x,s1.y), make_float2(s1.z,s1.w)};
                #pragma unroll
                for (int i = 0; i < 8; i++) {
                    float2 qq = make_float2(qa[i], qa[i]);
                    #pragma unroll
                    for (int j = 0; j < 4; j++) acc[i][j] = ffma2(qq, sb[j], acc[i][j]);
                }
            }
        }
        __syncthreads();
    }

    // epilogue: write S + per-p max
    if (act) {
        const int pA = tn / HWd;
        const int pB = (tn + 7) / HWd;
        float mA = -1e30f, mB = -1e30f;
        #pragma unroll
        for (int i = 0; i < 8; i++) {
            int m = tm + i;
            if (m >= HWd) continue;
            #pragma unroll
            for (int j4 = 0; j4 < 4; j4++) {
                int j = tn + 2*j4;
                float sx = acc[i][j4].x, sy = acc[i][j4].y;
                if (j < Pd*HWd) {
                    int p = j / HWd, nn = j - p*HWd;
                    g_S[((size_t)bq*Pd + p)*SMATS + m*HWd + nn] = sx;
                    if (p == pA) mA = fmaxf(mA, sx); else mB = fmaxf(mB, sx);
                }
                if (j + 1 < Pd*HWd) {
                    int p = (j+1) / HWd, nn = (j+1) - p*HWd;
                    g_S[((size_t)bq*Pd + p)*SMATS + m*HWd + nn] = sy;
                    if (p == pA) mA = fmaxf(mA, sy); else mB = fmaxf(mB, sy);
                }
            }
        }
        atomicMax(&smaxs[pA], ordf(mA));
        if (pB != pA && pB < Pd && mB > -1e29f) atomicMax(&smaxs[pB], ordf(mB));
    }
    __syncthreads();
    if (t < Pd) g_Smax[(size_t)bq*Pd + t] = unordf(smaxs[t]);
}

// ---------------- kernel 4: linear Sinkhorn + logits ----------------
// grid 3000 = (bq,p). 128 threads: rows in warps 0-1, cols in warps 2-3.
__global__ void __launch_bounds__(128) sinkhorn_kernel() {
    __shared__ __align__(16) float Ssh[HWd*50];
    __shared__ __align__(16) float Ksh[HWd*50];
    __shared__ float ash[HWd], bsh[HWd];
    __shared__ float2 ush2[25], vsh2[25];
    __shared__ float red[4];
    float* ush = (float*)ush2;
    float* vsh = (float*)vsh2;

    const int t = threadIdx.x;
    const int idx = blockIdx.x;
    const float* Sg = g_S + (size_t)idx*SMATS;
    const float Smax = g_Smax[idx];

    for (int i = t; i < HWd*50; i += 128) {
        int m = i / 50, n = i - m*50;
        float v = (n < HWd) ? Sg[m*HWd + n] : 0.f;
        Ssh[i] = v;
        Ksh[i] = (n < HWd) ? __expf((v - Smax) * INV_EPS) : 0.f;
    }
    if (t < HWd) {
        ash[t] = g_ma[(size_t)idx*HWd + t];
        bsh[t] = g_mb[(size_t)idx*HWd + t];
        vsh[t] = 1.0f;
    }
    if (t == 49) { vsh[49] = 0.f; ush[49] = 0.f; }
    __syncthreads();

    const bool isrow = (t < HWd);
    const bool iscol = (t >= 64 && t < 64 + HWd);
    const int rc = isrow ? t : (iscol ? t - 64 : 0);

    float2 Kreg[25];
    if (isrow) {
        #pragma unroll
        for (int k = 0; k < 25; k++) Kreg[k] = *(const float2*)&Ksh[t*50 + 2*k];
    }
    if (iscol) {
        #pragma unroll
        for (int k = 0; k < 24; k++)
            Kreg[k] = make_float2(Ksh[(2*k)*50 + rc], Ksh[(2*k+1)*50 + rc]);
        Kreg[24] = make_float2(Ksh[48*50 + rc], 0.f);
    }
    const float marg = isrow ? ash[t] : (iscol ? bsh[rc] : 0.f);

    #pragma unroll 1
    for (int it = 0; it < S_ITERS; it++) {
        if (isrow) {
            float2 a0 = make_float2(0,0), a1 = a0, a2 = a0, a3 = a0;
            #pragma unroll
            for (int k = 0; k < 24; k += 4) {
                a0 = ffma2(Kreg[k+0], vsh2[k+0], a0);
                a1 = ffma2(Kreg[k+1], vsh2[k+1], a1);
                a2 = ffma2(Kreg[k+2], vsh2[k+2], a2);
                a3 = ffma2(Kreg[k+3], vsh2[k+3], a3);
            }
            a0 = ffma2(Kreg[24], vsh2[24], a0);
            float s = ((a0.x + a0.y) + (a1.x + a1.y)) + ((a2.x + a2.y) + (a3.x + a3.y));
            ush[t] = __fdividef(marg, s);
        }
        __syncthreads();
        if (iscol) {
            float2 a0 = make_float2(0,0), a1 = a0, a2 = a0, a3 = a0;
            #pragma unroll
            for (int k = 0; k < 24; k += 4) {
                a0 = ffma2(Kreg[k+0], ush2[k+0], a0);
                a1 = ffma2(Kreg[k+1], ush2[k+1], a1);
                a2 = ffma2(Kreg[k+2], ush2[k+2], a2);
                a3 = ffma2(Kreg[k+3], ush2[k+3], a3);
            }
            a0 = ffma2(Kreg[24], ush2[24], a0);
            float s = ((a0.x + a0.y) + (a1.x + a1.y)) + ((a2.x + a2.y) + (a3.x + a3.y));
            vsh[rc] = __fdividef(marg, s);
        }
        __syncthreads();
    }

    // logits = TEMPER * sum S .* (u K v)
    float part = 0.f;
    for (int i = t; i < HWd*50; i += 128) {
        int m = i / 50, n = i - m*50;
        part += Ssh[i] * Ksh[i] * ush[m] * vsh[n];
    }
    #pragma unroll
    for (int o = 16; o; o >>= 1) part += __shfl_xor_sync(0xffffffffu, part, o);
    if ((t & 31) == 0) red[t >> 5] = part;
    __syncthreads();
    if (t == 0) g_logits[idx] = TEMPER * (red[0] + red[1] + red[2] + red[3]);
}

// ---------------- kernel 5: cross-entropy loss ----------------
__global__ void loss_kernel(const int* __restrict__ qy, float* __restrict__ out) {
    __shared__ float red[8];
    const int t = threadIdx.x;
    float s = 0.f;
    for (int r = t; r < BQd; r += 256) {
        float l[Pd];
        #pragma unroll
        for (int k = 0; k < Pd; k++) l[k] = g_logits[r*Pd + k];
        float mx = l[0];
        #pragma unroll
        for (int k = 1; k < Pd; k++) mx = fmaxf(mx, l[k]);
        float se = 0.f;
        #pragma unroll
        for (int k = 0; k < Pd; k++) se += expf(l[k] - mx);
        float lse = mx + logf(se);
        s += lse - l[qy[r]];
    }
    #pragma unroll
    for (int o = 16; o; o >>= 1) s += __shfl_xor_sync(0xffffffffu, s, o);
    if ((t & 31) == 0) red[t >> 5] = s;
    __syncthreads();
    if (t == 0) {
        float tot = 0.f;
        #pragma unroll
        for (int i = 0; i < 8; i++) tot += red[i];
        out[0] = tot * (1.0f / BQd);
    }
}

// ---------------- launch ---------------------------------------------------
extern "C" void kernel_launch(void* const* d_in, const int* in_sizes, int n_in,
                              void* d_out, int out_size) {
    const float* sup = (const float*)d_in[0];
    const float* qry = (const float*)d_in[1];
    const int*   qy  = (const int*)d_in[3];
    float* out = (float*)d_out;

    const int smem_sup = (IMG + 2*HWd) * (int)sizeof(float);
    const int smem_qry = (IMG + 2*HWd + Pd*Cd + Pd*HWd + Pd) * (int)sizeof(float);
    cudaFuncSetAttribute(prep_sup, cudaFuncAttributeMaxDynamicSharedMemorySize, smem_sup);
    cudaFuncSetAttribute(prep_qry, cudaFuncAttributeMaxDynamicSharedMemorySize, smem_qry);

    prep_sup<<<Bd*Pd, 512, smem_sup>>>(sup);
    prep_qry<<<BQd, 512, smem_qry>>>(qry);
    w2_kernel<<<Bd*Pd, 256>>>(sup);
    sgemm_kernel<<<BQd, 256>>>();
    sinkhorn_kernel<<<NMAT, 128>>>();
    loss_kernel<<<1, 256>>>(qy, out);
}

// round 5
// speedup vs baseline: 1.6990x; 1.1115x over previous
#include <cuda_runtime.h>
#include <cuda_bf16.h>
#include <stdint.h>
#include <math.h>

// Problem constants (fixed by setup_inputs)
#define Bd   8
#define Pd   5
#define Qd   75
#define Cd   640
#define HWd  49
#define BQd  (Bd*Qd)          // 600
#define NMAT (Bd*Qd*Pd)       // 3000
#define IMG  (Cd*HWd)         // 31360
#define SMATS   2404          // padded per-matrix stride for g_S
#define TEMPER  12.5f
#define INV_EPS 20.0f
#define S_ITERS 100

#define Nn   248              // 5*49 padded (rows 245-247 stay zero)
#define CP   320              // 640 bf16 / 2 per uint32

// ---------------- scratch (device globals; zero-initialized) ----------------
__device__ uint32_t g_qbf_hi[(size_t)BQd*HWd*CP];   // query bf16 hi pairs [bq][m][c/2]
__device__ uint32_t g_qbf_lo[(size_t)BQd*HWd*CP];
__device__ uint32_t g_sbf_hi[(size_t)Bd*Nn*CP];     // support bf16 hi [b][n][c/2]
__device__ uint32_t g_sbf_lo[(size_t)Bd*Nn*CP];
__device__ float g_sgap[Bd*Pd*Cd];
__device__ float g_qgap[BQd*Cd];
__device__ float g_ma[NMAT*HWd];
__device__ float g_mb[NMAT*HWd];
__device__ float g_S[(size_t)NMAT*SMATS];
__device__ float g_Smax[NMAT];
__device__ float g_logits[NMAT];

// ---------------- helpers ----------------
__device__ __forceinline__ float2 ffma2(float2 a, float2 b, float2 c) {
    float2 d;
    asm("fma.rn.f32x2 %0, %1, %2, %3;"
        : "=l"(reinterpret_cast<unsigned long long&>(d))
        : "l"(reinterpret_cast<unsigned long long&>(a)),
          "l"(reinterpret_cast<unsigned long long&>(b)),
          "l"(reinterpret_cast<unsigned long long&>(c)));
    return d;
}
__device__ __forceinline__ unsigned ordf(float f) {
    unsigned u = __float_as_uint(f);
    return (u & 0x80000000u) ? ~u : (u | 0x80000000u);
}
__device__ __forceinline__ float unordf(unsigned u) {
    return (u & 0x80000000u) ? __uint_as_float(u & 0x7fffffffu) : __uint_as_float(~u);
}

// mma.sync m16n8k16 bf16 (HMMA fallback path; baseline PTX, works on sm_103)
__device__ __forceinline__ void mma16816(float* d,
    uint32_t a0, uint32_t a1, uint32_t a2, uint32_t a3,
    uint32_t b0, uint32_t b1) {
    asm volatile("mma.sync.aligned.m16n8k16.row.col.f32.bf16.bf16.f32 "
        "{%0,%1,%2,%3}, {%4,%5,%6,%7}, {%8,%9}, {%0,%1,%2,%3};"
        : "+f"(d[0]), "+f"(d[1]), "+f"(d[2]), "+f"(d[3])
        : "r"(a0), "r"(a1), "r"(a2), "r"(a3), "r"(b0), "r"(b1));
}

extern __shared__ float sh_dyn[];

// ---------------- kernel 1a: support prep ----------------
__global__ void prep_sup(const float* __restrict__ x) {
    float* img   = sh_dyn;
    float* cmean = sh_dyn + IMG;
    float* crn   = cmean + HWd;
    const int t = threadIdx.x;
    const int bp = blockIdx.x, b = bp / Pd, p = bp % Pd;

    const float4* src = (const float4*)(x + (size_t)bp*IMG);
    float4* dst = (float4*)img;
    for (int i = t; i < IMG/4; i += 512) dst[i] = src[i];
    __syncthreads();

    const int w = t >> 5, lane = t & 31;
    for (int m = w; m < HWd; m += 16) {
        float s = 0.f;
        for (int c = lane; c < Cd; c += 32) s += img[c*HWd + m];
        #pragma unroll
        for (int o = 16; o; o >>= 1) s += __shfl_xor_sync(0xffffffffu, s, o);
        float mean = s * (1.0f/Cd);
        float ss = 0.f;
        for (int c = lane; c < Cd; c += 32) { float d = img[c*HWd + m] - mean; ss += d*d; }
        #pragma unroll
        for (int o = 16; o; o >>= 1) ss += __shfl_xor_sync(0xffffffffu, ss, o);
        if (lane == 0) { cmean[m] = mean; crn[m] = 1.0f / fmaxf(sqrtf(ss), 1e-8f); }
    }
    __syncthreads();

    for (int c = t; c < Cd; c += 512) {
        float g = 0.f;
        #pragma unroll 7
        for (int m = 0; m < HWd; m++) g += img[c*HWd + m];
        g_sgap[(size_t)bp*Cd + c] = g * (1.0f/HWd);
    }
    // bf16 hi/lo transposed write: [n=p*49+nn][c]
    for (int j = t; j < HWd*CP; j += 512) {
        int nn = j / CP, cp = j - nn*CP, c = 2*cp;
        float v0 = (img[c*HWd + nn]       - cmean[nn]) * crn[nn];
        float v1 = (img[(c+1)*HWd + nn]   - cmean[nn]) * crn[nn];
        __nv_bfloat162 hi2 = __floats2bfloat162_rn(v0, v1);
        __nv_bfloat162 lo2 = __floats2bfloat162_rn(v0 - __bfloat162float(hi2.x),
                                                   v1 - __bfloat162float(hi2.y));
        size_t o = ((size_t)b*Nn + p*HWd + nn)*CP + cp;
        g_sbf_hi[o] = *reinterpret_cast<uint32_t*>(&hi2);
        g_sbf_lo[o] = *reinterpret_cast<uint32_t*>(&lo2);
    }
}

// ---------------- kernel 1b: query prep + w1 marginals ----------------
__global__ void prep_qry(const float* __restrict__ x) {
    float* img   = sh_dyn;
    float* cmean = sh_dyn + IMG;
    float* crn   = cmean + HWd;
    float* sgb   = crn + HWd;        // Pd*Cd
    float* wa    = sgb + Pd*Cd;      // 245
    float* rs    = wa + Pd*HWd;      // 5
    const int t = threadIdx.x;
    const int bq = blockIdx.x, b = bq / Qd;

    const float4* src = (const float4*)(x + (size_t)bq*IMG);
    float4* dst = (float4*)img;
    for (int i = t; i < IMG/4; i += 512) dst[i] = src[i];
    for (int i = t; i < Pd*Cd; i += 512) sgb[i] = g_sgap[(size_t)b*Pd*Cd + i];
    __syncthreads();

    const int w = t >> 5, lane = t & 31;
    for (int m = w; m < HWd; m += 16) {
        float s = 0.f;
        for (int c = lane; c < Cd; c += 32) s += img[c*HWd + m];
        #pragma unroll
        for (int o = 16; o; o >>= 1) s += __shfl_xor_sync(0xffffffffu, s, o);
        float mean = s * (1.0f/Cd);
        float ss = 0.f;
        for (int c = lane; c < Cd; c += 32) { float d = img[c*HWd + m] - mean; ss += d*d; }
        #pragma unroll
        for (int o = 16; o; o >>= 1) ss += __shfl_xor_sync(0xffffffffu, ss, o);
        if (lane == 0) { cmean[m] = mean; crn[m] = 1.0f / fmaxf(sqrtf(ss), 1e-8f); }
    }

    for (int c = t; c < Cd; c += 512) {
        float g = 0.f;
        #pragma unroll 7
        for (int m = 0; m < HWd; m++) g += img[c*HWd + m];
        g_qgap[(size_t)bq*Cd + c] = g * (1.0f/HWd);
    }

    if (t < Pd*HWd) {
        const int p = t / HWd, m = t - p*HWd;
        const float* sgp = sgb + p*Cd;
        float acc = 0.f;
        #pragma unroll 4
        for (int c = 0; c < Cd; c++) acc += img[c*HWd + m] * sgp[c];
        wa[t] = (fmaxf(acc, 0.f) + 1e-3f) + 1e-5f;
    }
    __syncthreads();
    if (t < Pd) {
        float s = 0.f;
        for (int m = 0; m < HWd; m++) s += wa[t*HWd + m];
        rs[t] = 1.0f / s;
    }
    __syncthreads();
    if (t < Pd*HWd) {
        const int p = t / HWd;
        g_ma[((size_t)bq*Pd + p)*HWd + (t - p*HWd)] = wa[t] * rs[p];
    }

    for (int j = t; j < HWd*CP; j += 512) {
        int m = j / CP, cp = j - m*CP, c = 2*cp;
        float v0 = (img[c*HWd + m]     - cmean[m]) * crn[m];
        float v1 = (img[(c+1)*HWd + m] - cmean[m]) * crn[m];
        __nv_bfloat162 hi2 = __floats2bfloat162_rn(v0, v1);
        __nv_bfloat162 lo2 = __floats2bfloat162_rn(v0 - __bfloat162float(hi2.x),
                                                   v1 - __bfloat162float(hi2.y));
        size_t o = ((size_t)bq*HWd + m)*CP + cp;
        g_qbf_hi[o] = *reinterpret_cast<uint32_t*>(&hi2);
        g_qbf_lo[o] = *reinterpret_cast<uint32_t*>(&lo2);
    }
}

// ---------------- kernel 2: w2 marginals ----------------
__global__ void __launch_bounds__(256) w2_kernel(const float* __restrict__ sup) {
    __shared__ float sch[32*HWd];
    __shared__ float gch[Qd*32];
    __shared__ float wb[Qd*HWd];
    __shared__ float rsum[Qd];
    const int t = threadIdx.x;
    const int bp = blockIdx.x, b = bp / Pd, p = bp % Pd;
    const bool act = t < Pd*HWd;
    const int n = t % HWd, qg = t / HWd;

    float acc[15];
    #pragma unroll
    for (int j = 0; j < 15; j++) acc[j] = 0.f;

    for (int ch = 0; ch < 20; ch++) {
        for (int i = t; i < 32*HWd; i += 256)
            sch[i] = sup[(size_t)bp*IMG + ch*(32*HWd) + i];
        for (int i = t; i < Qd*32; i += 256) {
            int q = i / 32, cc = i - q*32;
            gch[i] = g_qgap[((size_t)b*Qd + q)*Cd + ch*32 + cc];
        }
        __syncthreads();
        if (act) {
            #pragma unroll 4
            for (int cc = 0; cc < 32; cc++) {
                float s = sch[cc*HWd + n];
                #pragma unroll
                for (int j = 0; j < 15; j++)
                    acc[j] += s * gch[(qg*15 + j)*32 + cc];
            }
        }
        __syncthreads();
    }
    if (act) {
        #pragma unroll
        for (int j = 0; j < 15; j++)
            wb[(qg*15 + j)*HWd + n] = (fmaxf(acc[j], 0.f) + 1e-3f) + 1e-5f;
    }
    __syncthreads();
    if (t < Qd) {
        float s = 0.f;
        for (int k = 0; k < HWd; k++) s += wb[t*HWd + k];
        rsum[t] = 1.0f / s;
    }
    __syncthreads();
    if (act) {
        #pragma unroll
        for (int j = 0; j < 15; j++) {
            int q = qg*15 + j;
            g_mb[(((size_t)b*Qd + q)*Pd + p)*HWd + n] = wb[q*HWd + n] * rsum[q];
        }
    }
}

// ---------------- kernel 3: mma.sync bf16-split S-GEMM ----------------
// grid 600 = (b,q). D[64,256] = A[64,640] . B[256,640]^T (49x245 valid),
// 3 bf16 passes: hi*hi + hi*lo + lo*hi. 8 warps = 2(M) x 4(N).
// SMEM rows use 20-word stride -> conflict-free fragment LDS.
#define AHW 0
#define ALW 1280
#define BHW 2560
#define BLW 7680
#define GEMM_SMEM (12800*4)

__global__ void __launch_bounds__(256) sgemm_mma_kernel() {
    uint32_t* smw = (uint32_t*)sh_dyn;
    uint4* smw4 = (uint4*)sh_dyn;
    __shared__ unsigned smax_sh[Pd];
    const int t = threadIdx.x;
    const int bq = blockIdx.x, b = bq / Qd;
    const int warp = t >> 5, lane = t & 31;
    const int wm = warp >> 2, wn = warp & 3;
    const int gid = lane >> 2, tid4 = lane & 3;
    if (t < Pd) smax_sh[t] = ordf(-1e30f);

    float acc[2][8][4];
    #pragma unroll
    for (int i = 0; i < 2; i++)
        #pragma unroll
        for (int j = 0; j < 8; j++)
            #pragma unroll
            for (int k = 0; k < 4; k++) acc[i][j][k] = 0.f;

    const uint4* qh = (const uint4*)g_qbf_hi + (size_t)bq*HWd*80;
    const uint4* ql = (const uint4*)g_qbf_lo + (size_t)bq*HWd*80;
    const uint4* sh = (const uint4*)g_sbf_hi + (size_t)b*Nn*80;
    const uint4* sl = (const uint4*)g_sbf_lo + (size_t)b*Nn*80;

    #pragma unroll 1
    for (int ch = 0; ch < 20; ch++) {
        __syncthreads();
        // stage A (64 rows x 4 uint4, hi+lo)
        for (int i = t; i < 512; i += 256) {
            int arr = i >> 8, rem = i & 255, row = rem >> 2, seg = rem & 3;
            int rowc = (row < HWd) ? row : (HWd-1);
            uint4 v = (arr ? ql : qh)[rowc*80 + ch*4 + seg];
            smw4[(arr ? ALW/4 : AHW/4) + row*5 + seg] = v;
        }
        // stage B (256 rows x 4 uint4, hi+lo)
        for (int i = t; i < 2048; i += 256) {
            int arr = i >> 10, rem = i & 1023, row = rem >> 2, seg = rem & 3;
            int rowc = (row < Nn) ? row : (Nn-1);
            uint4 v = (arr ? sl : sh)[rowc*80 + ch*4 + seg];
            smw4[(arr ? BLW/4 : BHW/4) + row*5 + seg] = v;
        }
        __syncthreads();

        #pragma unroll
        for (int ks = 0; ks < 2; ks++) {
            const int ko = ks*8;
            uint32_t ahf[2][4], alf[2][4];
            #pragma unroll
            for (int ms = 0; ms < 2; ms++) {
                int r0 = wm*32 + ms*16 + gid;
                int w0 = r0*20 + tid4 + ko;
                int w1 = (r0+8)*20 + tid4 + ko;
                ahf[ms][0] = smw[AHW + w0];
                ahf[ms][1] = smw[AHW + w1];
                ahf[ms][2] = smw[AHW + w0 + 4];
                ahf[ms][3] = smw[AHW + w1 + 4];
                alf[ms][0] = smw[ALW + w0];
                alf[ms][1] = smw[ALW + w1];
                alf[ms][2] = smw[ALW + w0 + 4];
                alf[ms][3] = smw[ALW + w1 + 4];
            }
            #pragma unroll
            for (int ns = 0; ns < 8; ns++) {
                int n0 = wn*64 + ns*8 + gid;
                int wb = n0*20 + tid4 + ko;
                uint32_t bh0 = smw[BHW + wb], bh1 = smw[BHW + wb + 4];
                uint32_t bl0 = smw[BLW + wb], bl1 = smw[BLW + wb + 4];
                #pragma unroll
                for (int ms = 0; ms < 2; ms++) {
                    mma16816(acc[ms][ns], ahf[ms][0], ahf[ms][1], ahf[ms][2], ahf[ms][3], bh0, bh1);
                    mma16816(acc[ms][ns], ahf[ms][0], ahf[ms][1], ahf[ms][2], ahf[ms][3], bl0, bl1);
                    mma16816(acc[ms][ns], alf[ms][0], alf[ms][1], alf[ms][2], alf[ms][3], bh0, bh1);
                }
            }
        }
    }

    // Epilogue: write g_S + per-p max
    float pm[3] = {-1e30f, -1e30f, -1e30f};
    const int pbase = (wn*64) / HWd;
    #pragma unroll
    for (int ms = 0; ms < 2; ms++) {
        #pragma unroll
        for (int half = 0; half < 2; half++) {
            int m = wm*32 + ms*16 + gid + half*8;
            if (m >= HWd) continue;
            #pragma unroll
            for (int ns = 0; ns < 8; ns++) {
                int colb = wn*64 + ns*8 + tid4*2;
                #pragma unroll
                for (int e = 0; e < 2; e++) {
                    int col = colb + e;
                    if (col < Pd*HWd) {
                        float v = acc[ms][ns][half*2 + e];
                        int p = col / HWd, nn = col - p*HWd;
                        g_S[((size_t)bq*Pd + p)*SMATS + m*HWd + nn] = v;
                        int d = p - pbase;
                        if (d == 0) pm[0] = fmaxf(pm[0], v);
                        else if (d == 1) pm[1] = fmaxf(pm[1], v);
                        else pm[2] = fmaxf(pm[2], v);
                    }
                }
            }
        }
    }
    #pragma unroll
    for (int j = 0; j < 3; j++) {
        if (pbase + j < Pd && pm[j] > -1e29f)
            atomicMax(&smax_sh[pbase + j], ordf(pm[j]));
    }
    __syncthreads();
    if (t < Pd) g_Smax[(size_t)bq*Pd + t] = unordf(smax_sh[t]);
}

// ---------------- kernel 4: linear Sinkhorn + logits ----------------
__global__ void __launch_bounds__(128) sinkhorn_kernel() {
    __shared__ __align__(16) float Ssh[HWd*50];
    __shared__ __align__(16) float Ksh[HWd*50];
    __shared__ float ash[HWd], bsh[HWd];
    __shared__ float2 ush2[25], vsh2[25];
    __shared__ float red[4];
    float* ush = (float*)ush2;
    float* vsh = (float*)vsh2;

    const int t = threadIdx.x;
    const int idx = blockIdx.x;
    const float* Sg = g_S + (size_t)idx*SMATS;
    const float Smax = g_Smax[idx];

    for (int i = t; i < HWd*50; i += 128) {
        int m = i / 50, n = i - m*50;
        float v = (n < HWd) ? Sg[m*HWd + n] : 0.f;
        Ssh[i] = v;
        Ksh[i] = (n < HWd) ? __expf((v - Smax) * INV_EPS) : 0.f;
    }
    if (t < HWd) {
        ash[t] = g_ma[(size_t)idx*HWd + t];
        bsh[t] = g_mb[(size_t)idx*HWd + t];
        vsh[t] = 1.0f;
    }
    if (t == 49) { vsh[49] = 0.f; ush[49] = 0.f; }
    __syncthreads();

    const bool isrow = (t < HWd);
    const bool iscol = (t >= 64 && t < 64 + HWd);
    const int rc = isrow ? t : (iscol ? t - 64 : 0);

    float2 Kreg[25];
    if (isrow) {
        #pragma unroll
        for (int k = 0; k < 25; k++) Kreg[k] = *(const float2*)&Ksh[t*50 + 2*k];
    }
    if (iscol) {
        #pragma unroll
        for (int k = 0; k < 24; k++)
            Kreg[k] = make_float2(Ksh[(2*k)*50 + rc], Ksh[(2*k+1)*50 + rc]);
        Kreg[24] = make_float2(Ksh[48*50 + rc], 0.f);
    }
    const float marg = isrow ? ash[t] : (iscol ? bsh[rc] : 0.f);

    #pragma unroll 1
    for (int it = 0; it < S_ITERS; it++) {
        if (isrow) {
            float2 a0 = make_float2(0,0), a1 = a0, a2 = a0, a3 = a0;
            #pragma unroll
            for (int k = 0; k < 24; k += 4) {
                a0 = ffma2(Kreg[k+0], vsh2[k+0], a0);
                a1 = ffma2(Kreg[k+1], vsh2[k+1], a1);
                a2 = ffma2(Kreg[k+2], vsh2[k+2], a2);
                a3 = ffma2(Kreg[k+3], vsh2[k+3], a3);
            }
            a0 = ffma2(Kreg[24], vsh2[24], a0);
            float s = ((a0.x + a0.y) + (a1.x + a1.y)) + ((a2.x + a2.y) + (a3.x + a3.y));
            ush[t] = __fdividef(marg, s);
        }
        __syncthreads();
        if (iscol) {
            float2 a0 = make_float2(0,0), a1 = a0, a2 = a0, a3 = a0;
            #pragma unroll
            for (int k = 0; k < 24; k += 4) {
                a0 = ffma2(Kreg[k+0], ush2[k+0], a0);
                a1 = ffma2(Kreg[k+1], ush2[k+1], a1);
                a2 = ffma2(Kreg[k+2], ush2[k+2], a2);
                a3 = ffma2(Kreg[k+3], ush2[k+3], a3);
            }
            a0 = ffma2(Kreg[24], ush2[24], a0);
            float s = ((a0.x + a0.y) + (a1.x + a1.y)) + ((a2.x + a2.y) + (a3.x + a3.y));
            vsh[rc] = __fdividef(marg, s);
        }
        __syncthreads();
    }

    float part = 0.f;
    for (int i = t; i < HWd*50; i += 128) {
        int m = i / 50, n = i - m*50;
        part += Ssh[i] * Ksh[i] * ush[m] * vsh[n];
    }
    #pragma unroll
    for (int o = 16; o; o >>= 1) part += __shfl_xor_sync(0xffffffffu, part, o);
    if ((t & 31) == 0) red[t >> 5] = part;
    __syncthreads();
    if (t == 0) g_logits[idx] = TEMPER * (red[0] + red[1] + red[2] + red[3]);
}

// ---------------- kernel 5: cross-entropy loss ----------------
__global__ void loss_kernel(const int* __restrict__ qy, float* __restrict__ out) {
    __shared__ float red[8];
    const int t = threadIdx.x;
    float s = 0.f;
    for (int r = t; r < BQd; r += 256) {
        float l[Pd];
        #pragma unroll
        for (int k = 0; k < Pd; k++) l[k] = g_logits[r*Pd + k];
        float mx = l[0];
        #pragma unroll
        for (int k = 1; k < Pd; k++) mx = fmaxf(mx, l[k]);
        float se = 0.f;
        #pragma unroll
        for (int k = 0; k < Pd; k++) se += expf(l[k] - mx);
        float lse = mx + logf(se);
        s += lse - l[qy[r]];
    }
    #pragma unroll
    for (int o = 16; o; o >>= 1) s += __shfl_xor_sync(0xffffffffu, s, o);
    if ((t & 31) == 0) red[t >> 5] = s;
    __syncthreads();
    if (t == 0) {
        float tot = 0.f;
        #pragma unroll
        for (int i = 0; i < 8; i++) tot += red[i];
        out[0] = tot * (1.0f / BQd);
    }
}

// ---------------- launch ---------------------------------------------------
extern "C" void kernel_launch(void* const* d_in, const int* in_sizes, int n_in,
                              void* d_out, int out_size) {
    const float* sup = (const float*)d_in[0];
    const float* qry = (const float*)d_in[1];
    const int*   qy  = (const int*)d_in[3];
    float* out = (float*)d_out;

    const int smem_sup = (IMG + 2*HWd) * (int)sizeof(float);
    const int smem_qry = (IMG + 2*HWd + Pd*Cd + Pd*HWd + Pd) * (int)sizeof(float);
    cudaFuncSetAttribute(prep_sup, cudaFuncAttributeMaxDynamicSharedMemorySize, smem_sup);
    cudaFuncSetAttribute(prep_qry, cudaFuncAttributeMaxDynamicSharedMemorySize, smem_qry);
    cudaFuncSetAttribute(sgemm_mma_kernel, cudaFuncAttributeMaxDynamicSharedMemorySize, GEMM_SMEM);

    prep_sup<<<Bd*Pd, 512, smem_sup>>>(sup);
    prep_qry<<<BQd, 512, smem_qry>>>(qry);
    w2_kernel<<<Bd*Pd, 256>>>(sup);
    sgemm_mma_kernel<<<BQd, 256, GEMM_SMEM>>>();
    sinkhorn_kernel<<<NMAT, 128>>>();
    loss_kernel<<<1, 256>>>(qy, out);
}

// round 6
// speedup vs baseline: 1.9911x; 1.1720x over previous
#include <cuda_runtime.h>
#include <cuda_bf16.h>
#include <stdint.h>
#include <math.h>

// Problem constants (fixed by setup_inputs)
#define Bd   8
#define Pd   5
#define Qd   75
#define Cd   640
#define HWd  49
#define BQd  (Bd*Qd)          // 600
#define NMAT (Bd*Qd*Pd)       // 3000
#define IMG  (Cd*HWd)         // 31360
#define SMATS   2404          // padded per-matrix stride for g_S
#define TEMPER  12.5f
#define INV_EPS 20.0f
#define S_ITERS 100

#define Nn   248              // 5*49 padded (rows 245-247 stay zero)
#define CP   320              // 640 bf16 / 2 per uint32
#define MROWS (Qd*HWd)        // 3675 packed query rows per b
#define MT_PER_B 58           // ceil(3675/64)
#define NGBLK (Bd*MT_PER_B*2) // 928

// ---------------- scratch (device globals; zero-initialized) ----------------
__device__ uint32_t g_qbf_hi[(size_t)BQd*HWd*CP];   // query bf16 hi pairs [bq][m][c/2]
__device__ uint32_t g_qbf_lo[(size_t)BQd*HWd*CP];
__device__ uint32_t g_sbf_hi[(size_t)Bd*Nn*CP];     // support bf16 hi [b][n][c/2]
__device__ uint32_t g_sbf_lo[(size_t)Bd*Nn*CP];
__device__ float g_sgap[Bd*Pd*Cd];
__device__ float g_qgap[BQd*Cd];
__device__ float g_ma[NMAT*HWd];
__device__ float g_mb[NMAT*HWd];
__device__ float g_S[(size_t)NMAT*SMATS];
__device__ float g_logits[NMAT];

// ---------------- helpers ----------------
__device__ __forceinline__ float2 ffma2(float2 a, float2 b, float2 c) {
    float2 d;
    asm("fma.rn.f32x2 %0, %1, %2, %3;"
        : "=l"(reinterpret_cast<unsigned long long&>(d))
        : "l"(reinterpret_cast<unsigned long long&>(a)),
          "l"(reinterpret_cast<unsigned long long&>(b)),
          "l"(reinterpret_cast<unsigned long long&>(c)));
    return d;
}

// mma.sync m16n8k16 bf16 (HMMA path; baseline PTX, works on sm_103)
__device__ __forceinline__ void mma16816(float* d,
    uint32_t a0, uint32_t a1, uint32_t a2, uint32_t a3,
    uint32_t b0, uint32_t b1) {
    asm volatile("mma.sync.aligned.m16n8k16.row.col.f32.bf16.bf16.f32 "
        "{%0,%1,%2,%3}, {%4,%5,%6,%7}, {%8,%9}, {%0,%1,%2,%3};"
        : "+f"(d[0]), "+f"(d[1]), "+f"(d[2]), "+f"(d[3])
        : "r"(a0), "r"(a1), "r"(a2), "r"(a3), "r"(b0), "r"(b1));
}

__device__ __forceinline__ uint32_t smem_u32(const void* p) {
    uint32_t a;
    asm("{ .reg .u64 t; cvta.to.shared.u64 t, %1; cvt.u32.u64 %0, t; }" : "=r"(a) : "l"(p));
    return a;
}
__device__ __forceinline__ void cp_async16(uint32_t dst, const void* src) {
    asm volatile("cp.async.cg.shared.global [%0], [%1], 16;" :: "r"(dst), "l"(src));
}
#define CP_COMMIT() asm volatile("cp.async.commit_group;" ::: "memory")
#define CP_WAIT1()  asm volatile("cp.async.wait_group 1;" ::: "memory")
#define CP_WAIT0()  asm volatile("cp.async.wait_group 0;" ::: "memory")

extern __shared__ float sh_dyn[];

// ---------------- kernel 1a: support prep ----------------
__global__ void prep_sup(const float* __restrict__ x) {
    float* img   = sh_dyn;
    float* cmean = sh_dyn + IMG;
    float* crn   = cmean + HWd;
    const int t = threadIdx.x;
    const int bp = blockIdx.x, b = bp / Pd, p = bp % Pd;

    const float4* src = (const float4*)(x + (size_t)bp*IMG);
    float4* dst = (float4*)img;
    for (int i = t; i < IMG/4; i += 512) dst[i] = src[i];
    __syncthreads();

    const int w = t >> 5, lane = t & 31;
    for (int m = w; m < HWd; m += 16) {
        float s = 0.f;
        for (int c = lane; c < Cd; c += 32) s += img[c*HWd + m];
        #pragma unroll
        for (int o = 16; o; o >>= 1) s += __shfl_xor_sync(0xffffffffu, s, o);
        float mean = s * (1.0f/Cd);
        float ss = 0.f;
        for (int c = lane; c < Cd; c += 32) { float d = img[c*HWd + m] - mean; ss += d*d; }
        #pragma unroll
        for (int o = 16; o; o >>= 1) ss += __shfl_xor_sync(0xffffffffu, ss, o);
        if (lane == 0) { cmean[m] = mean; crn[m] = 1.0f / fmaxf(sqrtf(ss), 1e-8f); }
    }
    __syncthreads();

    for (int c = t; c < Cd; c += 512) {
        float g = 0.f;
        #pragma unroll 7
        for (int m = 0; m < HWd; m++) g += img[c*HWd + m];
        g_sgap[(size_t)bp*Cd + c] = g * (1.0f/HWd);
    }
    for (int j = t; j < HWd*CP; j += 512) {
        int nn = j / CP, cp = j - nn*CP, c = 2*cp;
        float v0 = (img[c*HWd + nn]       - cmean[nn]) * crn[nn];
        float v1 = (img[(c+1)*HWd + nn]   - cmean[nn]) * crn[nn];
        __nv_bfloat162 hi2 = __floats2bfloat162_rn(v0, v1);
        __nv_bfloat162 lo2 = __floats2bfloat162_rn(v0 - __bfloat162float(hi2.x),
                                                   v1 - __bfloat162float(hi2.y));
        size_t o = ((size_t)b*Nn + p*HWd + nn)*CP + cp;
        g_sbf_hi[o] = *reinterpret_cast<uint32_t*>(&hi2);
        g_sbf_lo[o] = *reinterpret_cast<uint32_t*>(&lo2);
    }
}

// ---------------- kernel 1b: query prep + w1 marginals ----------------
__global__ void prep_qry(const float* __restrict__ x) {
    float* img   = sh_dyn;
    float* cmean = sh_dyn + IMG;
    float* crn   = cmean + HWd;
    float* sgb   = crn + HWd;        // Pd*Cd
    float* wa    = sgb + Pd*Cd;      // 245
    float* rs    = wa + Pd*HWd;      // 5
    const int t = threadIdx.x;
    const int bq = blockIdx.x, b = bq / Qd;

    const float4* src = (const float4*)(x + (size_t)bq*IMG);
    float4* dst = (float4*)img;
    for (int i = t; i < IMG/4; i += 512) dst[i] = src[i];
    for (int i = t; i < Pd*Cd; i += 512) sgb[i] = g_sgap[(size_t)b*Pd*Cd + i];
    __syncthreads();

    const int w = t >> 5, lane = t & 31;
    for (int m = w; m < HWd; m += 16) {
        float s = 0.f;
        for (int c = lane; c < Cd; c += 32) s += img[c*HWd + m];
        #pragma unroll
        for (int o = 16; o; o >>= 1) s += __shfl_xor_sync(0xffffffffu, s, o);
        float mean = s * (1.0f/Cd);
        float ss = 0.f;
        for (int c = lane; c < Cd; c += 32) { float d = img[c*HWd + m] - mean; ss += d*d; }
        #pragma unroll
        for (int o = 16; o; o >>= 1) ss += __shfl_xor_sync(0xffffffffu, ss, o);
        if (lane == 0) { cmean[m] = mean; crn[m] = 1.0f / fmaxf(sqrtf(ss), 1e-8f); }
    }

    for (int c = t; c < Cd; c += 512) {
        float g = 0.f;
        #pragma unroll 7
        for (int m = 0; m < HWd; m++) g += img[c*HWd + m];
        g_qgap[(size_t)bq*Cd + c] = g * (1.0f/HWd);
    }

    if (t < Pd*HWd) {
        const int p = t / HWd, m = t - p*HWd;
        const float* sgp = sgb + p*Cd;
        float acc = 0.f;
        #pragma unroll 4
        for (int c = 0; c < Cd; c++) acc += img[c*HWd + m] * sgp[c];
        wa[t] = (fmaxf(acc, 0.f) + 1e-3f) + 1e-5f;
    }
    __syncthreads();
    if (t < Pd) {
        float s = 0.f;
        for (int m = 0; m < HWd; m++) s += wa[t*HWd + m];
        rs[t] = 1.0f / s;
    }
    __syncthreads();
    if (t < Pd*HWd) {
        const int p = t / HWd;
        g_ma[((size_t)bq*Pd + p)*HWd + (t - p*HWd)] = wa[t] * rs[p];
    }

    for (int j = t; j < HWd*CP; j += 512) {
        int m = j / CP, cp = j - m*CP, c = 2*cp;
        float v0 = (img[c*HWd + m]     - cmean[m]) * crn[m];
        float v1 = (img[(c+1)*HWd + m] - cmean[m]) * crn[m];
        __nv_bfloat162 hi2 = __floats2bfloat162_rn(v0, v1);
        __nv_bfloat162 lo2 = __floats2bfloat162_rn(v0 - __bfloat162float(hi2.x),
                                                   v1 - __bfloat162float(hi2.y));
        size_t o = ((size_t)bq*HWd + m)*CP + cp;
        g_qbf_hi[o] = *reinterpret_cast<uint32_t*>(&hi2);
        g_qbf_lo[o] = *reinterpret_cast<uint32_t*>(&lo2);
    }
}

// ---------------- kernel 2: w2 marginals ----------------
__global__ void __launch_bounds__(256) w2_kernel(const float* __restrict__ sup) {
    __shared__ float sch[32*HWd];
    __shared__ float gch[Qd*32];
    __shared__ float wb[Qd*HWd];
    __shared__ float rsum[Qd];
    const int t = threadIdx.x;
    const int bp = blockIdx.x, b = bp / Pd, p = bp % Pd;
    const bool act = t < Pd*HWd;
    const int n = t % HWd, qg = t / HWd;

    float acc[15];
    #pragma unroll
    for (int j = 0; j < 15; j++) acc[j] = 0.f;

    for (int ch = 0; ch < 20; ch++) {
        for (int i = t; i < 32*HWd; i += 256)
            sch[i] = sup[(size_t)bp*IMG + ch*(32*HWd) + i];
        for (int i = t; i < Qd*32; i += 256) {
            int q = i / 32, cc = i - q*32;
            gch[i] = g_qgap[((size_t)b*Qd + q)*Cd + ch*32 + cc];
        }
        __syncthreads();
        if (act) {
            #pragma unroll 4
            for (int cc = 0; cc < 32; cc++) {
                float s = sch[cc*HWd + n];
                #pragma unroll
                for (int j = 0; j < 15; j++)
                    acc[j] += s * gch[(qg*15 + j)*32 + cc];
            }
        }
        __syncthreads();
    }
    if (act) {
        #pragma unroll
        for (int j = 0; j < 15; j++)
            wb[(qg*15 + j)*HWd + n] = (fmaxf(acc[j], 0.f) + 1e-3f) + 1e-5f;
    }
    __syncthreads();
    if (t < Qd) {
        float s = 0.f;
        for (int k = 0; k < HWd; k++) s += wb[t*HWd + k];
        rsum[t] = 1.0f / s;
    }
    __syncthreads();
    if (act) {
        #pragma unroll
        for (int j = 0; j < 15; j++) {
            int q = qg*15 + j;
            g_mb[(((size_t)b*Qd + q)*Pd + p)*HWd + n] = wb[q*HWd + n] * rsum[q];
        }
    }
}

// ---------------- kernel 3: packed-row cp.async double-buffered MMA GEMM ----
// grid 928 = (b, mtile, ntile). Tile M=64 (packed q*49+m rows), N=128, K=640.
// 3 bf16 passes: hi*hi + hi*lo + lo*hi. 8 warps (2M x 4N), warp tile 32x32.
// SMEM rows: K=64 chunk = 32 words, padded stride 36 words -> conflict-free.
#define RS    36
#define A_LO_W (64*RS)        // 2304
#define B_HI_W (128*RS)       // 4608
#define B_LO_W (256*RS)       // 9216
#define BUF_W  (384*RS)       // 13824 words per buffer
#define GEMM_SMEM (2*BUF_W*4) // 110592 bytes

__global__ void __launch_bounds__(256) sgemm_mma_kernel() {
    const int t = threadIdx.x;
    const int blk = blockIdx.x;
    const int b  = blk / (MT_PER_B*2);
    const int rem = blk - b*(MT_PER_B*2);
    const int mt = rem >> 1, nt = rem & 1;
    const int warp = t >> 5, lane = t & 31;
    const int wm = warp >> 2, wn = warp & 3;
    const int gid = lane >> 2, tid4 = lane & 3;

    const uint32_t smb = smem_u32(sh_dyn);
    const uint32_t* smw = (const uint32_t*)sh_dyn;

    const uint4* qh = (const uint4*)g_qbf_hi;
    const uint4* ql = (const uint4*)g_qbf_lo;
    const uint4* shv = (const uint4*)g_sbf_hi;
    const uint4* slv = (const uint4*)g_sbf_lo;

    float acc[2][4][4];
    #pragma unroll
    for (int i = 0; i < 2; i++)
        #pragma unroll
        for (int j = 0; j < 4; j++)
            #pragma unroll
            for (int k = 0; k < 4; k++) acc[i][j][k] = 0.f;

    // staging: A 64 rows (hi+lo), B 128 rows (hi+lo), 8 segs of 16B per row
    auto stage = [&](int ch, int bufsel) {
        const uint32_t dbase = smb + (uint32_t)bufsel*(BUF_W*4);
        #pragma unroll
        for (int k = 0; k < 4; k++) {               // A: 1024 xfers / 256 thr
            int i = t + k*256;
            int arr = i >> 9, remx = i & 511, row = remx >> 3, seg = remx & 7;
            int R = mt*64 + row; if (R > MROWS-1) R = MROWS-1;
            const uint4* s = (arr ? ql : qh) + ((size_t)b*MROWS + R)*80 + ch*8 + seg;
            cp_async16(dbase + (uint32_t)(arr*A_LO_W + row*RS + seg*4)*4, s);
        }
        #pragma unroll
        for (int k = 0; k < 8; k++) {               // B: 2048 xfers / 256 thr
            int i = t + k*256;
            int arr = i >> 10, remx = i & 1023, row = remx >> 3, seg = remx & 7;
            int N0 = nt*128 + row; if (N0 > Nn-1) N0 = Nn-1;
            const uint4* s = (arr ? slv : shv) + ((size_t)b*Nn + N0)*80 + ch*8 + seg;
            cp_async16(dbase + (uint32_t)(B_HI_W + arr*(B_HI_W) + row*RS + seg*4)*4, s);
        }
    };

    stage(0, 0);
    CP_COMMIT();

    #pragma unroll 1
    for (int ch = 0; ch < 10; ch++) {
        if (ch < 9) { stage(ch+1, (ch+1) & 1); CP_COMMIT(); CP_WAIT1(); }
        else        { CP_WAIT0(); }
        __syncthreads();

        const uint32_t* bw = smw + (ch & 1)*BUF_W;
        #pragma unroll
        for (int ks = 0; ks < 4; ks++) {
            uint32_t ahf[2][4], alf[2][4];
            #pragma unroll
            for (int ms = 0; ms < 2; ms++) {
                int r0 = wm*32 + ms*16 + gid;
                int w0 = r0*RS + tid4 + ks*8;
                int w1 = (r0+8)*RS + tid4 + ks*8;
                ahf[ms][0] = bw[w0];        ahf[ms][1] = bw[w1];
                ahf[ms][2] = bw[w0+4];      ahf[ms][3] = bw[w1+4];
                alf[ms][0] = bw[A_LO_W+w0]; alf[ms][1] = bw[A_LO_W+w1];
                alf[ms][2] = bw[A_LO_W+w0+4]; alf[ms][3] = bw[A_LO_W+w1+4];
            }
            #pragma unroll
            for (int ns = 0; ns < 4; ns++) {
                int n0 = wn*32 + ns*8 + gid;
                int wb = B_HI_W + n0*RS + tid4 + ks*8;
                uint32_t bh0 = bw[wb], bh1 = bw[wb+4];
                uint32_t bl0 = bw[wb+B_HI_W], bl1 = bw[wb+4+B_HI_W];
                #pragma unroll
                for (int ms = 0; ms < 2; ms++) {
                    mma16816(acc[ms][ns], ahf[ms][0], ahf[ms][1], ahf[ms][2], ahf[ms][3], bh0, bh1);
                    mma16816(acc[ms][ns], ahf[ms][0], ahf[ms][1], ahf[ms][2], ahf[ms][3], bl0, bl1);
                    mma16816(acc[ms][ns], alf[ms][0], alf[ms][1], alf[ms][2], alf[ms][3], bh0, bh1);
                }
            }
        }
        __syncthreads();
    }

    // Epilogue: write g_S (row R -> (q, m), col C -> (p, nn))
    #pragma unroll
    for (int ms = 0; ms < 2; ms++) {
        #pragma unroll
        for (int half = 0; half < 2; half++) {
            int R = mt*64 + wm*32 + ms*16 + gid + half*8;
            if (R >= MROWS) continue;
            int q = R / HWd, mm = R - q*HWd;
            float* dstq = g_S + ((size_t)(b*Qd + q)*Pd)*SMATS + mm*HWd;
            #pragma unroll
            for (int ns = 0; ns < 4; ns++) {
                #pragma unroll
                for (int e = 0; e < 2; e++) {
                    int C = nt*128 + wn*32 + ns*8 + tid4*2 + e;
                    if (C < Pd*HWd) {
                        int p = C / HWd, nn = C - p*HWd;
                        dstq[(size_t)p*SMATS + nn] = acc[ms][ns][half*2 + e];
                    }
                }
            }
        }
    }
}

// ---------------- kernel 4: linear Sinkhorn + logits (computes own Smax) ----
__global__ void __launch_bounds__(128) sinkhorn_kernel() {
    __shared__ __align__(16) float Ssh[HWd*50];
    __shared__ __align__(16) float Ksh[HWd*50];
    __shared__ float ash[HWd], bsh[HWd];
    __shared__ float2 ush2[25], vsh2[25];
    __shared__ float red[4];
    float* ush = (float*)ush2;
    float* vsh = (float*)vsh2;

    const int t = threadIdx.x;
    const int idx = blockIdx.x;
    const float* Sg = g_S + (size_t)idx*SMATS;

    float lmax = -1e30f;
    for (int i = t; i < HWd*50; i += 128) {
        int m = i / 50, n = i - m*50;
        float v = 0.f;
        if (n < HWd) { v = Sg[m*HWd + n]; lmax = fmaxf(lmax, v); }
        Ssh[i] = v;
    }
    #pragma unroll
    for (int o = 16; o; o >>= 1) lmax = fmaxf(lmax, __shfl_xor_sync(0xffffffffu, lmax, o));
    if ((t & 31) == 0) red[t >> 5] = lmax;
    if (t < HWd) {
        ash[t] = g_ma[(size_t)idx*HWd + t];
        bsh[t] = g_mb[(size_t)idx*HWd + t];
        vsh[t] = 1.0f;
    }
    if (t == 49) { vsh[49] = 0.f; ush[49] = 0.f; }
    __syncthreads();
    const float Smax = fmaxf(fmaxf(red[0], red[1]), fmaxf(red[2], red[3]));

    for (int i = t; i < HWd*50; i += 128) {
        int n = i % 50;
        Ksh[i] = (n < HWd) ? __expf((Ssh[i] - Smax) * INV_EPS) : 0.f;
    }
    __syncthreads();

    const bool isrow = (t < HWd);
    const bool iscol = (t >= 64 && t < 64 + HWd);
    const int rc = isrow ? t : (iscol ? t - 64 : 0);

    float2 Kreg[25];
    if (isrow) {
        #pragma unroll
        for (int k = 0; k < 25; k++) Kreg[k] = *(const float2*)&Ksh[t*50 + 2*k];
    }
    if (iscol) {
        #pragma unroll
        for (int k = 0; k < 24; k++)
            Kreg[k] = make_float2(Ksh[(2*k)*50 + rc], Ksh[(2*k+1)*50 + rc]);
        Kreg[24] = make_float2(Ksh[48*50 + rc], 0.f);
    }
    const float marg = isrow ? ash[t] : (iscol ? bsh[rc] : 0.f);

    #pragma unroll 1
    for (int it = 0; it < S_ITERS; it++) {
        if (isrow) {
            float2 a0 = make_float2(0,0), a1 = a0, a2 = a0, a3 = a0;
            #pragma unroll
            for (int k = 0; k < 24; k += 4) {
                a0 = ffma2(Kreg[k+0], vsh2[k+0], a0);
                a1 = ffma2(Kreg[k+1], vsh2[k+1], a1);
                a2 = ffma2(Kreg[k+2], vsh2[k+2], a2);
                a3 = ffma2(Kreg[k+3], vsh2[k+3], a3);
            }
            a0 = ffma2(Kreg[24], vsh2[24], a0);
            float s = ((a0.x + a0.y) + (a1.x + a1.y)) + ((a2.x + a2.y) + (a3.x + a3.y));
            ush[t] = __fdividef(marg, s);
        }
        __syncthreads();
        if (iscol) {
            float2 a0 = make_float2(0,0), a1 = a0, a2 = a0, a3 = a0;
            #pragma unroll
            for (int k = 0; k < 24; k += 4) {
                a0 = ffma2(Kreg[k+0], ush2[k+0], a0);
                a1 = ffma2(Kreg[k+1], ush2[k+1], a1);
                a2 = ffma2(Kreg[k+2], ush2[k+2], a2);
                a3 = ffma2(Kreg[k+3], ush2[k+3], a3);
            }
            a0 = ffma2(Kreg[24], ush2[24], a0);
            float s = ((a0.x + a0.y) + (a1.x + a1.y)) + ((a2.x + a2.y) + (a3.x + a3.y));
            vsh[rc] = __fdividef(marg, s);
        }
        __syncthreads();
    }

    float part = 0.f;
    for (int i = t; i < HWd*50; i += 128) {
        int m = i / 50, n = i - m*50;
        part += Ssh[i] * Ksh[i] * ush[m] * vsh[n];
    }
    #pragma unroll
    for (int o = 16; o; o >>= 1) part += __shfl_xor_sync(0xffffffffu, part, o);
    if ((t & 31) == 0) red[t >> 5] = part;
    __syncthreads();
    if (t == 0) g_logits[idx] = TEMPER * (red[0] + red[1] + red[2] + red[3]);
}

// ---------------- kernel 5: cross-entropy loss ----------------
__global__ void loss_kernel(const int* __restrict__ qy, float* __restrict__ out) {
    __shared__ float red[8];
    const int t = threadIdx.x;
    float s = 0.f;
    for (int r = t; r < BQd; r += 256) {
        float l[Pd];
        #pragma unroll
        for (int k = 0; k < Pd; k++) l[k] = g_logits[r*Pd + k];
        float mx = l[0];
        #pragma unroll
        for (int k = 1; k < Pd; k++) mx = fmaxf(mx, l[k]);
        float se = 0.f;
        #pragma unroll
        for (int k = 0; k < Pd; k++) se += expf(l[k] - mx);
        float lse = mx + logf(se);
        s += lse - l[qy[r]];
    }
    #pragma unroll
    for (int o = 16; o; o >>= 1) s += __shfl_xor_sync(0xffffffffu, s, o);
    if ((t & 31) == 0) red[t >> 5] = s;
    __syncthreads();
    if (t == 0) {
        float tot = 0.f;
        #pragma unroll
        for (int i = 0; i < 8; i++) tot += red[i];
        out[0] = tot * (1.0f / BQd);
    }
}

// ---------------- launch ---------------------------------------------------
extern "C" void kernel_launch(void* const* d_in, const int* in_sizes, int n_in,
                              void* d_out, int out_size) {
    const float* sup = (const float*)d_in[0];
    const float* qry = (const float*)d_in[1];
    const int*   qy  = (const int*)d_in[3];
    float* out = (float*)d_out;

    const int smem_sup = (IMG + 2*HWd) * (int)sizeof(float);
    const int smem_qry = (IMG + 2*HWd + Pd*Cd + Pd*HWd + Pd) * (int)sizeof(float);
    cudaFuncSetAttribute(prep_sup, cudaFuncAttributeMaxDynamicSharedMemorySize, smem_sup);
    cudaFuncSetAttribute(prep_qry, cudaFuncAttributeMaxDynamicSharedMemorySize, smem_qry);
    cudaFuncSetAttribute(sgemm_mma_kernel, cudaFuncAttributeMaxDynamicSharedMemorySize, GEMM_SMEM);

    prep_sup<<<Bd*Pd, 512, smem_sup>>>(sup);
    prep_qry<<<BQd, 512, smem_qry>>>(qry);
    w2_kernel<<<Bd*Pd, 256>>>(sup);
    sgemm_mma_kernel<<<NGBLK, 256, GEMM_SMEM>>>();
    sinkhorn_kernel<<<NMAT, 128>>>();
    loss_kernel<<<1, 256>>>(qy, out);
}

// round 7
// speedup vs baseline: 2.4277x; 1.2193x over previous
#include <cuda_runtime.h>
#include <cuda_bf16.h>
#include <stdint.h>
#include <math.h>

#define Bd   8
#define Pd   5
#define Qd   75
#define Cd   640
#define HWd  49
#define BQd  (Bd*Qd)          // 600
#define NMAT (Bd*Qd*Pd)       // 3000
#define IMG  (Cd*HWd)         // 31360
#define SMATS   2404
#define TEMPER  12.5f
#define INV_EPS 20.0f
#define S_ITERS 100

#define Nn   248
#define CP   320
#define MROWS (Qd*HWd)        // 3675
#define MT_PER_B 58
#define NGBLK (Bd*MT_PER_B*2) // 928
#define VP   52               // padded sinkhorn vector length

// ---------------- scratch ----------------
__device__ uint32_t g_qbf_hi[(size_t)BQd*HWd*CP];
__device__ uint32_t g_qbf_lo[(size_t)BQd*HWd*CP];
__device__ uint32_t g_sbf_hi[(size_t)Bd*Nn*CP];
__device__ uint32_t g_sbf_lo[(size_t)Bd*Nn*CP];
__device__ float g_sgap[Bd*Pd*Cd];
__device__ float g_qgap[BQd*Cd];
__device__ float g_ma[NMAT*HWd];
__device__ float g_mb[NMAT*HWd];
__device__ float g_S[(size_t)NMAT*SMATS];
__device__ float g_logits[NMAT];

// ---------------- helpers ----------------
__device__ __forceinline__ float2 ffma2(float2 a, float2 b, float2 c) {
    float2 d;
    asm("fma.rn.f32x2 %0, %1, %2, %3;"
        : "=l"(reinterpret_cast<unsigned long long&>(d))
        : "l"(reinterpret_cast<unsigned long long&>(a)),
          "l"(reinterpret_cast<unsigned long long&>(b)),
          "l"(reinterpret_cast<unsigned long long&>(c)));
    return d;
}
__device__ __forceinline__ void mma16816(float* d,
    uint32_t a0, uint32_t a1, uint32_t a2, uint32_t a3,
    uint32_t b0, uint32_t b1) {
    asm volatile("mma.sync.aligned.m16n8k16.row.col.f32.bf16.bf16.f32 "
        "{%0,%1,%2,%3}, {%4,%5,%6,%7}, {%8,%9}, {%0,%1,%2,%3};"
        : "+f"(d[0]), "+f"(d[1]), "+f"(d[2]), "+f"(d[3])
        : "r"(a0), "r"(a1), "r"(a2), "r"(a3), "r"(b0), "r"(b1));
}
__device__ __forceinline__ uint32_t smem_u32(const void* p) {
    uint32_t a;
    asm("{ .reg .u64 t; cvta.to.shared.u64 t, %1; cvt.u32.u64 %0, t; }" : "=r"(a) : "l"(p));
    return a;
}
__device__ __forceinline__ void cp_async16(uint32_t dst, const void* src) {
    asm volatile("cp.async.cg.shared.global [%0], [%1], 16;" :: "r"(dst), "l"(src));
}
#define CP_COMMIT() asm volatile("cp.async.commit_group;" ::: "memory")
#define CP_WAIT1()  asm volatile("cp.async.wait_group 1;" ::: "memory")
#define CP_WAIT0()  asm volatile("cp.async.wait_group 0;" ::: "memory")

extern __shared__ float sh_dyn[];

// ---------------- kernel 0: GAPs for all 640 images ----------------
__global__ void __launch_bounds__(256) gaps_kernel(const float* __restrict__ sup,
                                                   const float* __restrict__ qry) {
    const int bid = blockIdx.x;
    const float* src;
    float* dst;
    if (bid < Bd*Pd) { src = sup + (size_t)bid*IMG; dst = g_sgap + (size_t)bid*Cd; }
    else { int q = bid - Bd*Pd; src = qry + (size_t)q*IMG; dst = g_qgap + (size_t)q*Cd; }
    for (int c = threadIdx.x; c < Cd; c += 256) {
        const float* p = src + c*HWd;
        float s = 0.f;
        #pragma unroll 7
        for (int m = 0; m < HWd; m++) s += p[m];
        dst[c] = s * (1.0f/HWd);
    }
}

// ---------------- kernel 1: merged prep (sup: normalize+sbf+w2; qry: normalize+qbf+w1)
// grid 640: blocks 0..39 = (b,p) support, 40..639 = (b,q) query. 512 threads.
// SMEM floats: img[31360]; sup: sch@31360(1664), gch2@33024(2432), wb@35456(3675),
//   rsum@39131(75), cmean@39206(49), crn@39255(49)  -> 39304 total
// qry: sgb@31360(3200), wa@34560(245), rs@34805(5), cmean@34810, crn@34859
#define PREP_SMEM (39304*4)

__global__ void __launch_bounds__(512) prep_all(const float* __restrict__ sup,
                                                const float* __restrict__ qry) {
    float* img = sh_dyn;
    const int t = threadIdx.x;
    const int bid = blockIdx.x;
    const bool is_sup = bid < Bd*Pd;

    float* cmean; float* crn;
    if (is_sup) { cmean = sh_dyn + 39206; crn = sh_dyn + 39255; }
    else        { cmean = sh_dyn + 34810; crn = sh_dyn + 34859; }

    const float* src = is_sup ? (sup + (size_t)bid*IMG)
                              : (qry + (size_t)(bid - Bd*Pd)*IMG);
    {   // stage image
        const float4* s4 = (const float4*)src;
        float4* d4 = (float4*)img;
        for (int i = t; i < IMG/4; i += 512) d4[i] = s4[i];
    }
    __syncthreads();

    // per-column stats
    const int w = t >> 5, lane = t & 31;
    for (int m = w; m < HWd; m += 16) {
        float s = 0.f;
        for (int c = lane; c < Cd; c += 32) s += img[c*HWd + m];
        #pragma unroll
        for (int o = 16; o; o >>= 1) s += __shfl_xor_sync(0xffffffffu, s, o);
        float mean = s * (1.0f/Cd);
        float ss = 0.f;
        for (int c = lane; c < Cd; c += 32) { float d = img[c*HWd + m] - mean; ss += d*d; }
        #pragma unroll
        for (int o = 16; o; o >>= 1) ss += __shfl_xor_sync(0xffffffffu, ss, o);
        if (lane == 0) { cmean[m] = mean; crn[m] = 1.0f / fmaxf(sqrtf(ss), 1e-8f); }
    }
    __syncthreads();

    if (is_sup) {
        const int b = bid / Pd, p = bid % Pd;
        // normalized bf16 hi/lo write
        for (int j = t; j < HWd*CP; j += 512) {
            int nn = j / CP, cp = j - nn*CP, c = 2*cp;
            float v0 = (img[c*HWd + nn]     - cmean[nn]) * crn[nn];
            float v1 = (img[(c+1)*HWd + nn] - cmean[nn]) * crn[nn];
            __nv_bfloat162 hi2 = __floats2bfloat162_rn(v0, v1);
            __nv_bfloat162 lo2 = __floats2bfloat162_rn(v0 - __bfloat162float(hi2.x),
                                                       v1 - __bfloat162float(hi2.y));
            size_t o = ((size_t)b*Nn + p*HWd + nn)*CP + cp;
            g_sbf_hi[o] = *reinterpret_cast<uint32_t*>(&hi2);
            g_sbf_lo[o] = *reinterpret_cast<uint32_t*>(&lo2);
        }

        // ---- w2 GEMM: C[75,49] = qgap[75,640] x img[640,49] ----
        float* sch  = sh_dyn + 31360;   // [32][52]
        float* gch2 = sh_dyn + 33024;   // [32][76]
        float* wb   = sh_dyn + 35456;   // [75][49]
        float* rsum = sh_dyn + 39131;   // [75]
        for (int i = t; i < 1664; i += 512) sch[i] = 0.f;
        for (int i = t; i < 2432; i += 512) gch2[i] = 0.f;

        const int tx = t % 13, ty = t / 13;   // n-tile, q-tile (t<247 active)
        const bool act = t < 247;
        float2 acc2[4][2];
        #pragma unroll
        for (int i = 0; i < 4; i++) { acc2[i][0] = make_float2(0,0); acc2[i][1] = make_float2(0,0); }
        __syncthreads();

        for (int ch = 0; ch < 20; ch++) {
            for (int i = t; i < 32*HWd; i += 512) {
                int cc = i / HWd, n = i - cc*HWd;
                sch[cc*52 + n] = img[ch*(32*HWd) + i];
            }
            const int b75 = bid / Pd * Qd;
            for (int i = t; i < Qd*32; i += 512) {
                int q = i >> 5, cc = i & 31;
                gch2[cc*76 + q] = g_qgap[((size_t)b75 + q)*Cd + ch*32 + cc];
            }
            __syncthreads();
            if (act) {
                #pragma unroll 8
                for (int cc = 0; cc < 32; cc++) {
                    float4 s4 = *(const float4*)&sch[cc*52 + tx*4];
                    float4 g4 = *(const float4*)&gch2[cc*76 + ty*4];
                    float2 sA = make_float2(s4.x, s4.y), sB = make_float2(s4.z, s4.w);
                    float g[4] = {g4.x, g4.y, g4.z, g4.w};
                    #pragma unroll
                    for (int qi = 0; qi < 4; qi++) {
                        float2 gg = make_float2(g[qi], g[qi]);
                        acc2[qi][0] = ffma2(gg, sA, acc2[qi][0]);
                        acc2[qi][1] = ffma2(gg, sB, acc2[qi][1]);
                    }
                }
            }
            __syncthreads();
        }
        if (act) {
            #pragma unroll
            for (int qi = 0; qi < 4; qi++) {
                int q = ty*4 + qi;
                if (q >= Qd) continue;
                float vals[4] = {acc2[qi][0].x, acc2[qi][0].y, acc2[qi][1].x, acc2[qi][1].y};
                #pragma unroll
                for (int e = 0; e < 4; e++) {
                    int n = tx*4 + e;
                    if (n < HWd)
                        wb[q*HWd + n] = (fmaxf(vals[e], 0.f) + 1e-3f) + 1e-5f;
                }
            }
        }
        __syncthreads();
        if (t < Qd) {
            float s = 0.f;
            for (int k = 0; k < HWd; k++) s += wb[t*HWd + k];
            rsum[t] = 1.0f / s;
        }
        __syncthreads();
        for (int i = t; i < Qd*HWd; i += 512) {
            int q = i / HWd;
            g_mb[(((size_t)(bid/Pd)*Qd + q)*Pd + p)*HWd + (i - q*HWd)] = wb[i] * rsum[q];
        }
    } else {
        const int bq = bid - Bd*Pd, b = bq / Qd;
        float* sgb = sh_dyn + 31360;    // [5][640]
        float* wa  = sh_dyn + 34560;    // [245]
        float* rs  = sh_dyn + 34805;    // [5]
        for (int i = t; i < Pd*Cd; i += 512) sgb[i] = g_sgap[(size_t)b*Pd*Cd + i];
        __syncthreads();

        if (t < Pd*HWd) {
            const int p = t / HWd, m = t - p*HWd;
            const float* sgp = sgb + p*Cd;
            float acc = 0.f;
            #pragma unroll 4
            for (int c = 0; c < Cd; c++) acc += img[c*HWd + m] * sgp[c];
            wa[t] = (fmaxf(acc, 0.f) + 1e-3f) + 1e-5f;
        }
        __syncthreads();
        if (t < Pd) {
            float s = 0.f;
            for (int m = 0; m < HWd; m++) s += wa[t*HWd + m];
            rs[t] = 1.0f / s;
        }
        __syncthreads();
        if (t < Pd*HWd) {
            const int p = t / HWd;
            g_ma[((size_t)bq*Pd + p)*HWd + (t - p*HWd)] = wa[t] * rs[p];
        }

        for (int j = t; j < HWd*CP; j += 512) {
            int m = j / CP, cp = j - m*CP, c = 2*cp;
            float v0 = (img[c*HWd + m]     - cmean[m]) * crn[m];
            float v1 = (img[(c+1)*HWd + m] - cmean[m]) * crn[m];
            __nv_bfloat162 hi2 = __floats2bfloat162_rn(v0, v1);
            __nv_bfloat162 lo2 = __floats2bfloat162_rn(v0 - __bfloat162float(hi2.x),
                                                       v1 - __bfloat162float(hi2.y));
            size_t o = ((size_t)bq*HWd + m)*CP + cp;
            g_qbf_hi[o] = *reinterpret_cast<uint32_t*>(&hi2);
            g_qbf_lo[o] = *reinterpret_cast<uint32_t*>(&lo2);
        }
    }
}

// ---------------- kernel 2: packed-row cp.async double-buffered MMA GEMM ----
#define RS    36
#define A_LO_W (64*RS)
#define B_HI_W (128*RS)
#define BUF_W  (384*RS)
#define GEMM_SMEM (2*BUF_W*4)

__global__ void __launch_bounds__(256) sgemm_mma_kernel() {
    const int t = threadIdx.x;
    const int blk = blockIdx.x;
    const int b  = blk / (MT_PER_B*2);
    const int rem = blk - b*(MT_PER_B*2);
    const int mt = rem >> 1, nt = rem & 1;
    const int warp = t >> 5, lane = t & 31;
    const int wm = warp >> 2, wn = warp & 3;
    const int gid = lane >> 2, tid4 = lane & 3;

    const uint32_t smb = smem_u32(sh_dyn);
    const uint32_t* smw = (const uint32_t*)sh_dyn;

    const uint4* qh = (const uint4*)g_qbf_hi;
    const uint4* ql = (const uint4*)g_qbf_lo;
    const uint4* shv = (const uint4*)g_sbf_hi;
    const uint4* slv = (const uint4*)g_sbf_lo;

    float acc[2][4][4];
    #pragma unroll
    for (int i = 0; i < 2; i++)
        #pragma unroll
        for (int j = 0; j < 4; j++)
            #pragma unroll
            for (int k = 0; k < 4; k++) acc[i][j][k] = 0.f;

    auto stage = [&](int ch, int bufsel) {
        const uint32_t dbase = smb + (uint32_t)bufsel*(BUF_W*4);
        #pragma unroll
        for (int k = 0; k < 4; k++) {
            int i = t + k*256;
            int arr = i >> 9, remx = i & 511, row = remx >> 3, seg = remx & 7;
            int R = mt*64 + row; if (R > MROWS-1) R = MROWS-1;
            const uint4* s = (arr ? ql : qh) + ((size_t)b*MROWS + R)*80 + ch*8 + seg;
            cp_async16(dbase + (uint32_t)(arr*A_LO_W + row*RS + seg*4)*4, s);
        }
        #pragma unroll
        for (int k = 0; k < 8; k++) {
            int i = t + k*256;
            int arr = i >> 10, remx = i & 1023, row = remx >> 3, seg = remx & 7;
            int N0 = nt*128 + row; if (N0 > Nn-1) N0 = Nn-1;
            const uint4* s = (arr ? slv : shv) + ((size_t)b*Nn + N0)*80 + ch*8 + seg;
            cp_async16(dbase + (uint32_t)(B_HI_W + arr*(B_HI_W) + row*RS + seg*4)*4, s);
        }
    };

    stage(0, 0);
    CP_COMMIT();

    #pragma unroll 1
    for (int ch = 0; ch < 10; ch++) {
        if (ch < 9) { stage(ch+1, (ch+1) & 1); CP_COMMIT(); CP_WAIT1(); }
        else        { CP_WAIT0(); }
        __syncthreads();

        const uint32_t* bw = smw + (ch & 1)*BUF_W;
        #pragma unroll
        for (int ks = 0; ks < 4; ks++) {
            uint32_t ahf[2][4], alf[2][4];
            #pragma unroll
            for (int ms = 0; ms < 2; ms++) {
                int r0 = wm*32 + ms*16 + gid;
                int w0 = r0*RS + tid4 + ks*8;
                int w1 = (r0+8)*RS + tid4 + ks*8;
                ahf[ms][0] = bw[w0];        ahf[ms][1] = bw[w1];
                ahf[ms][2] = bw[w0+4];      ahf[ms][3] = bw[w1+4];
                alf[ms][0] = bw[A_LO_W+w0]; alf[ms][1] = bw[A_LO_W+w1];
                alf[ms][2] = bw[A_LO_W+w0+4]; alf[ms][3] = bw[A_LO_W+w1+4];
            }
            #pragma unroll
            for (int ns = 0; ns < 4; ns++) {
                int n0 = wn*32 + ns*8 + gid;
                int wb = B_HI_W + n0*RS + tid4 + ks*8;
                uint32_t bh0 = bw[wb], bh1 = bw[wb+4];
                uint32_t bl0 = bw[wb+B_HI_W], bl1 = bw[wb+4+B_HI_W];
                #pragma unroll
                for (int ms = 0; ms < 2; ms++) {
                    mma16816(acc[ms][ns], ahf[ms][0], ahf[ms][1], ahf[ms][2], ahf[ms][3], bh0, bh1);
                    mma16816(acc[ms][ns], ahf[ms][0], ahf[ms][1], ahf[ms][2], ahf[ms][3], bl0, bl1);
                    mma16816(acc[ms][ns], alf[ms][0], alf[ms][1], alf[ms][2], alf[ms][3], bh0, bh1);
                }
            }
        }
        __syncthreads();
    }

    #pragma unroll
    for (int ms = 0; ms < 2; ms++) {
        #pragma unroll
        for (int half = 0; half < 2; half++) {
            int R = mt*64 + wm*32 + ms*16 + gid + half*8;
            if (R >= MROWS) continue;
            int q = R / HWd, mm = R - q*HWd;
            float* dstq = g_S + ((size_t)(b*Qd + q)*Pd)*SMATS + mm*HWd;
            #pragma unroll
            for (int ns = 0; ns < 4; ns++) {
                #pragma unroll
                for (int e = 0; e < 2; e++) {
                    int C = nt*128 + wn*32 + ns*8 + tid4*2 + e;
                    if (C < Pd*HWd) {
                        int p = C / HWd, nn = C - p*HWd;
                        dstq[(size_t)p*SMATS + nn] = acc[ms][ns][half*2 + e];
                    }
                }
            }
        }
    }
}

// ---------------- kernel 3: linear Sinkhorn + logits (float4 vectors) ----
__global__ void __launch_bounds__(128) sinkhorn_kernel() {
    __shared__ __align__(16) float Ssh[HWd*VP];
    __shared__ __align__(16) float Ksh[HWd*VP];
    __shared__ __align__(16) float ush[VP];
    __shared__ __align__(16) float vsh[VP];
    __shared__ float ash[HWd], bsh[HWd];
    __shared__ float red[4];

    const int t = threadIdx.x;
    const int idx = blockIdx.x;
    const float* Sg = g_S + (size_t)idx*SMATS;

    float lmax = -1e30f;
    for (int i = t; i < HWd*VP; i += 128) {
        int m = i / VP, n = i - m*VP;
        float v = 0.f;
        if (n < HWd) { v = Sg[m*HWd + n]; lmax = fmaxf(lmax, v); }
        Ssh[i] = v;
    }
    #pragma unroll
    for (int o = 16; o; o >>= 1) lmax = fmaxf(lmax, __shfl_xor_sync(0xffffffffu, lmax, o));
    if ((t & 31) == 0) red[t >> 5] = lmax;
    if (t < HWd) {
        ash[t] = g_ma[(size_t)idx*HWd + t];
        bsh[t] = g_mb[(size_t)idx*HWd + t];
    }
    if (t < VP) { vsh[t] = (t < HWd) ? 1.0f : 0.f; ush[t] = 0.f; }
    __syncthreads();
    const float Smax = fmaxf(fmaxf(red[0], red[1]), fmaxf(red[2], red[3]));

    for (int i = t; i < HWd*VP; i += 128) {
        int n = i % VP;
        Ksh[i] = (n < HWd) ? __expf((Ssh[i] - Smax) * INV_EPS) : 0.f;
    }
    __syncthreads();

    const bool isrow = (t < HWd);
    const bool iscol = (t >= 64 && t < 64 + HWd);
    const int rc = isrow ? t : (iscol ? t - 64 : 0);
    const float4* ush4 = (const float4*)ush;
    const float4* vsh4 = (const float4*)vsh;

    float4 Kr[13];
    if (isrow) {
        const float4* kr4 = (const float4*)Ksh + t*13;
        #pragma unroll
        for (int j = 0; j < 13; j++) Kr[j] = kr4[j];
    }
    if (iscol) {
        #pragma unroll
        for (int j = 0; j < 12; j++)
            Kr[j] = make_float4(Ksh[(4*j)*VP + rc], Ksh[(4*j+1)*VP + rc],
                                Ksh[(4*j+2)*VP + rc], Ksh[(4*j+3)*VP + rc]);
        Kr[12] = make_float4(Ksh[48*VP + rc], 0.f, 0.f, 0.f);
    }
    const float marg = isrow ? ash[t] : (iscol ? bsh[rc] : 0.f);

    #pragma unroll 1
    for (int it = 0; it < S_ITERS; it++) {
        if (isrow) {
            float2 a0 = make_float2(0,0), a1 = a0, a2 = a0, a3 = a0;
            #pragma unroll
            for (int j = 0; j < 12; j += 2) {
                float4 v0 = vsh4[j], v1 = vsh4[j+1];
                a0 = ffma2(make_float2(Kr[j].x, Kr[j].y),   make_float2(v0.x, v0.y), a0);
                a1 = ffma2(make_float2(Kr[j].z, Kr[j].w),   make_float2(v0.z, v0.w), a1);
                a2 = ffma2(make_float2(Kr[j+1].x, Kr[j+1].y), make_float2(v1.x, v1.y), a2);
                a3 = ffma2(make_float2(Kr[j+1].z, Kr[j+1].w), make_float2(v1.z, v1.w), a3);
            }
            {
                float4 v0 = vsh4[12];
                a0 = ffma2(make_float2(Kr[12].x, Kr[12].y), make_float2(v0.x, v0.y), a0);
                a1 = ffma2(make_float2(Kr[12].z, Kr[12].w), make_float2(v0.z, v0.w), a1);
            }
            float s = ((a0.x + a0.y) + (a1.x + a1.y)) + ((a2.x + a2.y) + (a3.x + a3.y));
            ush[t] = __fdividef(marg, s);
        }
        __syncthreads();
        if (iscol) {
            float2 a0 = make_float2(0,0), a1 = a0, a2 = a0, a3 = a0;
            #pragma unroll
            for (int j = 0; j < 12; j += 2) {
                float4 v0 = ush4[j], v1 = ush4[j+1];
                a0 = ffma2(make_float2(Kr[j].x, Kr[j].y),   make_float2(v0.x, v0.y), a0);
                a1 = ffma2(make_float2(Kr[j].z, Kr[j].w),   make_float2(v0.z, v0.w), a1);
                a2 = ffma2(make_float2(Kr[j+1].x, Kr[j+1].y), make_float2(v1.x, v1.y), a2);
                a3 = ffma2(make_float2(Kr[j+1].z, Kr[j+1].w), make_float2(v1.z, v1.w), a3);
            }
            {
                float4 v0 = ush4[12];
                a0 = ffma2(make_float2(Kr[12].x, Kr[12].y), make_float2(v0.x, v0.y), a0);
                a1 = ffma2(make_float2(Kr[12].z, Kr[12].w), make_float2(v0.z, v0.w), a1);
            }
            float s = ((a0.x + a0.y) + (a1.x + a1.y)) + ((a2.x + a2.y) + (a3.x + a3.y));
            vsh[rc] = __fdividef(marg, s);
        }
        __syncthreads();
    }

    // logits = TEMPER * sum_m u[m] * sum_n S[m,n]K[m,n]v[n]  (rows use reg-cached Kr)
    float part = 0.f;
    if (isrow) {
        const float4* sr4 = (const float4*)Ssh + t*13;
        float rsum = 0.f;
        #pragma unroll
        for (int j = 0; j < 13; j++) {
            float4 s4 = sr4[j], v4 = vsh4[j];
            rsum += s4.x*Kr[j].x*v4.x + s4.y*Kr[j].y*v4.y
                  + s4.z*Kr[j].z*v4.z + s4.w*Kr[j].w*v4.w;
        }
        part = ush[t] * rsum;
    }
    #pragma unroll
    for (int o = 16; o; o >>= 1) part += __shfl_xor_sync(0xffffffffu, part, o);
    if ((t & 31) == 0) red[t >> 5] = part;
    __syncthreads();
    if (t == 0) g_logits[idx] = TEMPER * (red[0] + red[1] + red[2] + red[3]);
}

// ---------------- kernel 4: cross-entropy loss ----------------
__global__ void loss_kernel(const int* __restrict__ qy, float* __restrict__ out) {
    __shared__ float red[8];
    const int t = threadIdx.x;
    float s = 0.f;
    for (int r = t; r < BQd; r += 256) {
        float l[Pd];
        #pragma unroll
        for (int k = 0; k < Pd; k++) l[k] = g_logits[r*Pd + k];
        float mx = l[0];
        #pragma unroll
        for (int k = 1; k < Pd; k++) mx = fmaxf(mx, l[k]);
        float se = 0.f;
        #pragma unroll
        for (int k = 0; k < Pd; k++) se += expf(l[k] - mx);
        float lse = mx + logf(se);
        s += lse - l[qy[r]];
    }
    #pragma unroll
    for (int o = 16; o; o >>= 1) s += __shfl_xor_sync(0xffffffffu, s, o);
    if ((t & 31) == 0) red[t >> 5] = s;
    __syncthreads();
    if (t == 0) {
        float tot = 0.f;
        #pragma unroll
        for (int i = 0; i < 8; i++) tot += red[i];
        out[0] = tot * (1.0f / BQd);
    }
}

// ---------------- launch ---------------------------------------------------
extern "C" void kernel_launch(void* const* d_in, const int* in_sizes, int n_in,
                              void* d_out, int out_size) {
    const float* sup = (const float*)d_in[0];
    const float* qry = (const float*)d_in[1];
    const int*   qy  = (const int*)d_in[3];
    float* out = (float*)d_out;

    cudaFuncSetAttribute(prep_all, cudaFuncAttributeMaxDynamicSharedMemorySize, PREP_SMEM);
    cudaFuncSetAttribute(sgemm_mma_kernel, cudaFuncAttributeMaxDynamicSharedMemorySize, GEMM_SMEM);

    gaps_kernel<<<Bd*Pd + BQd, 256>>>(sup, qry);
    prep_all<<<Bd*Pd + BQd, 512, PREP_SMEM>>>(sup, qry);
    sgemm_mma_kernel<<<NGBLK, 256, GEMM_SMEM>>>();
    sinkhorn_kernel<<<NMAT, 128>>>();
    loss_kernel<<<1, 256>>>(qy, out);
}

// round 8
// speedup vs baseline: 2.4377x; 1.0041x over previous
#include <cuda_runtime.h>
#include <cuda_bf16.h>
#include <stdint.h>
#include <math.h>

#define Bd   8
#define Pd   5
#define Qd   75
#define Cd   640
#define HWd  49
#define BQd  (Bd*Qd)          // 600
#define NMAT (Bd*Qd*Pd)       // 3000
#define IMG  (Cd*HWd)         // 31360
#define SMATS   2404
#define TEMPER  12.5f
#define INV_EPS 20.0f
#define S_ITERS 100

#define Nn   248
#define CP   320
#define MROWS (Qd*HWd)        // 3675
#define MT_PER_B 58
#define NGBLK (Bd*MT_PER_B*2) // 928
#define VP   52               // padded sinkhorn vector length

// ---------------- scratch ----------------
__device__ uint32_t g_qbf_hi[(size_t)BQd*HWd*CP];
__device__ uint32_t g_qbf_lo[(size_t)BQd*HWd*CP];
__device__ uint32_t g_sbf_hi[(size_t)Bd*Nn*CP];
__device__ uint32_t g_sbf_lo[(size_t)Bd*Nn*CP];
__device__ float g_sgap[Bd*Pd*Cd];
__device__ float g_qgap[BQd*Cd];
__device__ float g_ma[NMAT*HWd];
__device__ float g_mb[NMAT*HWd];
__device__ float g_S[(size_t)NMAT*SMATS];
__device__ float g_logits[NMAT];

// ---------------- helpers ----------------
__device__ __forceinline__ float2 ffma2(float2 a, float2 b, float2 c) {
    float2 d;
    asm("fma.rn.f32x2 %0, %1, %2, %3;"
        : "=l"(reinterpret_cast<unsigned long long&>(d))
        : "l"(reinterpret_cast<unsigned long long&>(a)),
          "l"(reinterpret_cast<unsigned long long&>(b)),
          "l"(reinterpret_cast<unsigned long long&>(c)));
    return d;
}
__device__ __forceinline__ void mma16816(float* d,
    uint32_t a0, uint32_t a1, uint32_t a2, uint32_t a3,
    uint32_t b0, uint32_t b1) {
    asm volatile("mma.sync.aligned.m16n8k16.row.col.f32.bf16.bf16.f32 "
        "{%0,%1,%2,%3}, {%4,%5,%6,%7}, {%8,%9}, {%0,%1,%2,%3};"
        : "+f"(d[0]), "+f"(d[1]), "+f"(d[2]), "+f"(d[3])
        : "r"(a0), "r"(a1), "r"(a2), "r"(a3), "r"(b0), "r"(b1));
}
__device__ __forceinline__ uint32_t smem_u32(const void* p) {
    uint32_t a;
    asm("{ .reg .u64 t; cvta.to.shared.u64 t, %1; cvt.u32.u64 %0, t; }" : "=r"(a) : "l"(p));
    return a;
}
__device__ __forceinline__ void cp_async16(uint32_t dst, const void* src) {
    asm volatile("cp.async.cg.shared.global [%0], [%1], 16;" :: "r"(dst), "l"(src));
}
#define CP_COMMIT() asm volatile("cp.async.commit_group;" ::: "memory")
#define CP_WAIT1()  asm volatile("cp.async.wait_group 1;" ::: "memory")
#define CP_WAIT0()  asm volatile("cp.async.wait_group 0;" ::: "memory")

// 49-length dot: K in registers (13 float4), v broadcast from SMEM (float4).
// Tail elements (49..51) are zero in both K pads and vector pads.
__device__ __forceinline__ float dot49(const float4* K, const float4* v4) {
    float2 a0 = make_float2(0,0), a1 = a0, a2 = a0, a3 = a0;
    #pragma unroll
    for (int j = 0; j < 12; j += 2) {
        float4 v0 = v4[j], v1 = v4[j+1];
        a0 = ffma2(make_float2(K[j].x,  K[j].y),   make_float2(v0.x, v0.y), a0);
        a1 = ffma2(make_float2(K[j].z,  K[j].w),   make_float2(v0.z, v0.w), a1);
        a2 = ffma2(make_float2(K[j+1].x,K[j+1].y), make_float2(v1.x, v1.y), a2);
        a3 = ffma2(make_float2(K[j+1].z,K[j+1].w), make_float2(v1.z, v1.w), a3);
    }
    float4 v0 = v4[12];
    a0 = ffma2(make_float2(K[12].x, K[12].y), make_float2(v0.x, v0.y), a0);
    a1 = ffma2(make_float2(K[12].z, K[12].w), make_float2(v0.z, v0.w), a1);
    return ((a0.x + a0.y) + (a1.x + a1.y)) + ((a2.x + a2.y) + (a3.x + a3.y));
}

extern __shared__ float sh_dyn[];

// ---------------- kernel 0: GAPs (smem-staged, coalesced) ----------------
#define GAPS_SMEM (IMG*4)
__global__ void __launch_bounds__(512) gaps_kernel(const float* __restrict__ sup,
                                                   const float* __restrict__ qry) {
    float* img = sh_dyn;
    const int bid = blockIdx.x;
    const int t = threadIdx.x;
    const float* src;
    float* dst;
    if (bid < Bd*Pd) { src = sup + (size_t)bid*IMG; dst = g_sgap + (size_t)bid*Cd; }
    else { int q = bid - Bd*Pd; src = qry + (size_t)q*IMG; dst = g_qgap + (size_t)q*Cd; }

    const float4* s4 = (const float4*)src;
    float4* d4 = (float4*)img;
    for (int i = t; i < IMG/4; i += 512) d4[i] = s4[i];
    __syncthreads();

    for (int c = t; c < Cd; c += 512) {
        const float* p = img + c*HWd;
        float s = 0.f;
        #pragma unroll 7
        for (int m = 0; m < HWd; m++) s += p[m];
        dst[c] = s * (1.0f/HWd);
    }
}

// ---------------- kernel 1: merged prep ----------------
#define PREP_SMEM (39304*4)
__global__ void __launch_bounds__(512) prep_all(const float* __restrict__ sup,
                                                const float* __restrict__ qry) {
    float* img = sh_dyn;
    const int t = threadIdx.x;
    const int bid = blockIdx.x;
    const bool is_sup = bid < Bd*Pd;

    float* cmean; float* crn;
    if (is_sup) { cmean = sh_dyn + 39206; crn = sh_dyn + 39255; }
    else        { cmean = sh_dyn + 34810; crn = sh_dyn + 34859; }

    const float* src = is_sup ? (sup + (size_t)bid*IMG)
                              : (qry + (size_t)(bid - Bd*Pd)*IMG);
    {
        const float4* s4 = (const float4*)src;
        float4* d4 = (float4*)img;
        for (int i = t; i < IMG/4; i += 512) d4[i] = s4[i];
    }
    __syncthreads();

    const int w = t >> 5, lane = t & 31;
    for (int m = w; m < HWd; m += 16) {
        float s = 0.f;
        for (int c = lane; c < Cd; c += 32) s += img[c*HWd + m];
        #pragma unroll
        for (int o = 16; o; o >>= 1) s += __shfl_xor_sync(0xffffffffu, s, o);
        float mean = s * (1.0f/Cd);
        float ss = 0.f;
        for (int c = lane; c < Cd; c += 32) { float d = img[c*HWd + m] - mean; ss += d*d; }
        #pragma unroll
        for (int o = 16; o; o >>= 1) ss += __shfl_xor_sync(0xffffffffu, ss, o);
        if (lane == 0) { cmean[m] = mean; crn[m] = 1.0f / fmaxf(sqrtf(ss), 1e-8f); }
    }
    __syncthreads();

    if (is_sup) {
        const int b = bid / Pd, p = bid % Pd;
        for (int j = t; j < HWd*CP; j += 512) {
            int nn = j / CP, cp = j - nn*CP, c = 2*cp;
            float v0 = (img[c*HWd + nn]     - cmean[nn]) * crn[nn];
            float v1 = (img[(c+1)*HWd + nn] - cmean[nn]) * crn[nn];
            __nv_bfloat162 hi2 = __floats2bfloat162_rn(v0, v1);
            __nv_bfloat162 lo2 = __floats2bfloat162_rn(v0 - __bfloat162float(hi2.x),
                                                       v1 - __bfloat162float(hi2.y));
            size_t o = ((size_t)b*Nn + p*HWd + nn)*CP + cp;
            g_sbf_hi[o] = *reinterpret_cast<uint32_t*>(&hi2);
            g_sbf_lo[o] = *reinterpret_cast<uint32_t*>(&lo2);
        }

        float* sch  = sh_dyn + 31360;
        float* gch2 = sh_dyn + 33024;
        float* wb   = sh_dyn + 35456;
        float* rsum = sh_dyn + 39131;
        for (int i = t; i < 1664; i += 512) sch[i] = 0.f;
        for (int i = t; i < 2432; i += 512) gch2[i] = 0.f;

        const int tx = t % 13, ty = t / 13;
        const bool act = t < 247;
        float2 acc2[4][2];
        #pragma unroll
        for (int i = 0; i < 4; i++) { acc2[i][0] = make_float2(0,0); acc2[i][1] = make_float2(0,0); }
        __syncthreads();

        for (int ch = 0; ch < 20; ch++) {
            for (int i = t; i < 32*HWd; i += 512) {
                int cc = i / HWd, n = i - cc*HWd;
                sch[cc*52 + n] = img[ch*(32*HWd) + i];
            }
            const int b75 = bid / Pd * Qd;
            for (int i = t; i < Qd*32; i += 512) {
                int q = i >> 5, cc = i & 31;
                gch2[cc*76 + q] = g_qgap[((size_t)b75 + q)*Cd + ch*32 + cc];
            }
            __syncthreads();
            if (act) {
                #pragma unroll 8
                for (int cc = 0; cc < 32; cc++) {
                    float4 s4 = *(const float4*)&sch[cc*52 + tx*4];
                    float4 g4 = *(const float4*)&gch2[cc*76 + ty*4];
                    float2 sA = make_float2(s4.x, s4.y), sB = make_float2(s4.z, s4.w);
                    float g[4] = {g4.x, g4.y, g4.z, g4.w};
                    #pragma unroll
                    for (int qi = 0; qi < 4; qi++) {
                        float2 gg = make_float2(g[qi], g[qi]);
                        acc2[qi][0] = ffma2(gg, sA, acc2[qi][0]);
                        acc2[qi][1] = ffma2(gg, sB, acc2[qi][1]);
                    }
                }
            }
            __syncthreads();
        }
        if (act) {
            #pragma unroll
            for (int qi = 0; qi < 4; qi++) {
                int q = ty*4 + qi;
                if (q >= Qd) continue;
                float vals[4] = {acc2[qi][0].x, acc2[qi][0].y, acc2[qi][1].x, acc2[qi][1].y};
                #pragma unroll
                for (int e = 0; e < 4; e++) {
                    int n = tx*4 + e;
                    if (n < HWd)
                        wb[q*HWd + n] = (fmaxf(vals[e], 0.f) + 1e-3f) + 1e-5f;
                }
            }
        }
        __syncthreads();
        if (t < Qd) {
            float s = 0.f;
            for (int k = 0; k < HWd; k++) s += wb[t*HWd + k];
            rsum[t] = 1.0f / s;
        }
        __syncthreads();
        for (int i = t; i < Qd*HWd; i += 512) {
            int q = i / HWd;
            g_mb[(((size_t)(bid/Pd)*Qd + q)*Pd + p)*HWd + (i - q*HWd)] = wb[i] * rsum[q];
        }
    } else {
        const int bq = bid - Bd*Pd, b = bq / Qd;
        float* sgb = sh_dyn + 31360;
        float* wa  = sh_dyn + 34560;
        float* rs  = sh_dyn + 34805;
        for (int i = t; i < Pd*Cd; i += 512) sgb[i] = g_sgap[(size_t)b*Pd*Cd + i];
        __syncthreads();

        if (t < Pd*HWd) {
            const int p = t / HWd, m = t - p*HWd;
            const float* sgp = sgb + p*Cd;
            float acc = 0.f;
            #pragma unroll 4
            for (int c = 0; c < Cd; c++) acc += img[c*HWd + m] * sgp[c];
            wa[t] = (fmaxf(acc, 0.f) + 1e-3f) + 1e-5f;
        }
        __syncthreads();
        if (t < Pd) {
            float s = 0.f;
            for (int m = 0; m < HWd; m++) s += wa[t*HWd + m];
            rs[t] = 1.0f / s;
        }
        __syncthreads();
        if (t < Pd*HWd) {
            const int p = t / HWd;
            g_ma[((size_t)bq*Pd + p)*HWd + (t - p*HWd)] = wa[t] * rs[p];
        }

        for (int j = t; j < HWd*CP; j += 512) {
            int m = j / CP, cp = j - m*CP, c = 2*cp;
            float v0 = (img[c*HWd + m]     - cmean[m]) * crn[m];
            float v1 = (img[(c+1)*HWd + m] - cmean[m]) * crn[m];
            __nv_bfloat162 hi2 = __floats2bfloat162_rn(v0, v1);
            __nv_bfloat162 lo2 = __floats2bfloat162_rn(v0 - __bfloat162float(hi2.x),
                                                       v1 - __bfloat162float(hi2.y));
            size_t o = ((size_t)bq*HWd + m)*CP + cp;
            g_qbf_hi[o] = *reinterpret_cast<uint32_t*>(&hi2);
            g_qbf_lo[o] = *reinterpret_cast<uint32_t*>(&lo2);
        }
    }
}

// ---------------- kernel 2: packed-row cp.async double-buffered MMA GEMM ----
#define RS    36
#define A_LO_W (64*RS)
#define B_HI_W (128*RS)
#define BUF_W  (384*RS)
#define GEMM_SMEM (2*BUF_W*4)

__global__ void __launch_bounds__(256) sgemm_mma_kernel() {
    const int t = threadIdx.x;
    const int blk = blockIdx.x;
    const int b  = blk / (MT_PER_B*2);
    const int rem = blk - b*(MT_PER_B*2);
    const int mt = rem >> 1, nt = rem & 1;
    const int warp = t >> 5, lane = t & 31;
    const int wm = warp >> 2, wn = warp & 3;
    const int gid = lane >> 2, tid4 = lane & 3;

    const uint32_t smb = smem_u32(sh_dyn);
    const uint32_t* smw = (const uint32_t*)sh_dyn;

    const uint4* qh = (const uint4*)g_qbf_hi;
    const uint4* ql = (const uint4*)g_qbf_lo;
    const uint4* shv = (const uint4*)g_sbf_hi;
    const uint4* slv = (const uint4*)g_sbf_lo;

    float acc[2][4][4];
    #pragma unroll
    for (int i = 0; i < 2; i++)
        #pragma unroll
        for (int j = 0; j < 4; j++)
            #pragma unroll
            for (int k = 0; k < 4; k++) acc[i][j][k] = 0.f;

    auto stage = [&](int ch, int bufsel) {
        const uint32_t dbase = smb + (uint32_t)bufsel*(BUF_W*4);
        #pragma unroll
        for (int k = 0; k < 4; k++) {
            int i = t + k*256;
            int arr = i >> 9, remx = i & 511, row = remx >> 3, seg = remx & 7;
            int R = mt*64 + row; if (R > MROWS-1) R = MROWS-1;
            const uint4* s = (arr ? ql : qh) + ((size_t)b*MROWS + R)*80 + ch*8 + seg;
            cp_async16(dbase + (uint32_t)(arr*A_LO_W + row*RS + seg*4)*4, s);
        }
        #pragma unroll
        for (int k = 0; k < 8; k++) {
            int i = t + k*256;
            int arr = i >> 10, remx = i & 1023, row = remx >> 3, seg = remx & 7;
            int N0 = nt*128 + row; if (N0 > Nn-1) N0 = Nn-1;
            const uint4* s = (arr ? slv : shv) + ((size_t)b*Nn + N0)*80 + ch*8 + seg;
            cp_async16(dbase + (uint32_t)(B_HI_W + arr*(B_HI_W) + row*RS + seg*4)*4, s);
        }
    };

    stage(0, 0);
    CP_COMMIT();

    #pragma unroll 1
    for (int ch = 0; ch < 10; ch++) {
        if (ch < 9) { stage(ch+1, (ch+1) & 1); CP_COMMIT(); CP_WAIT1(); }
        else        { CP_WAIT0(); }
        __syncthreads();

        const uint32_t* bw = smw + (ch & 1)*BUF_W;
        #pragma unroll
        for (int ks = 0; ks < 4; ks++) {
            uint32_t ahf[2][4], alf[2][4];
            #pragma unroll
            for (int ms = 0; ms < 2; ms++) {
                int r0 = wm*32 + ms*16 + gid;
                int w0 = r0*RS + tid4 + ks*8;
                int w1 = (r0+8)*RS + tid4 + ks*8;
                ahf[ms][0] = bw[w0];        ahf[ms][1] = bw[w1];
                ahf[ms][2] = bw[w0+4];      ahf[ms][3] = bw[w1+4];
                alf[ms][0] = bw[A_LO_W+w0]; alf[ms][1] = bw[A_LO_W+w1];
                alf[ms][2] = bw[A_LO_W+w0+4]; alf[ms][3] = bw[A_LO_W+w1+4];
            }
            #pragma unroll
            for (int ns = 0; ns < 4; ns++) {
                int n0 = wn*32 + ns*8 + gid;
                int wb = B_HI_W + n0*RS + tid4 + ks*8;
                uint32_t bh0 = bw[wb], bh1 = bw[wb+4];
                uint32_t bl0 = bw[wb+B_HI_W], bl1 = bw[wb+4+B_HI_W];
                #pragma unroll
                for (int ms = 0; ms < 2; ms++) {
                    mma16816(acc[ms][ns], ahf[ms][0], ahf[ms][1], ahf[ms][2], ahf[ms][3], bh0, bh1);
                    mma16816(acc[ms][ns], ahf[ms][0], ahf[ms][1], ahf[ms][2], ahf[ms][3], bl0, bl1);
                    mma16816(acc[ms][ns], alf[ms][0], alf[ms][1], alf[ms][2], alf[ms][3], bh0, bh1);
                }
            }
        }
        __syncthreads();
    }

    #pragma unroll
    for (int ms = 0; ms < 2; ms++) {
        #pragma unroll
        for (int half = 0; half < 2; half++) {
            int R = mt*64 + wm*32 + ms*16 + gid + half*8;
            if (R >= MROWS) continue;
            int q = R / HWd, mm = R - q*HWd;
            float* dstq = g_S + ((size_t)(b*Qd + q)*Pd)*SMATS + mm*HWd;
            #pragma unroll
            for (int ns = 0; ns < 4; ns++) {
                #pragma unroll
                for (int e = 0; e < 2; e++) {
                    int C = nt*128 + wn*32 + ns*8 + tid4*2 + e;
                    if (C < Pd*HWd) {
                        int p = C / HWd, nn = C - p*HWd;
                        dstq[(size_t)p*SMATS + nn] = acc[ms][ns][half*2 + e];
                    }
                }
            }
        }
    }
}

// ---------------- kernel 3: fused row+col Sinkhorn (64 thr, K row+col in regs)
__global__ void __launch_bounds__(64) sinkhorn_kernel() {
    __shared__ __align__(16) float Ssh[HWd*VP];
    __shared__ __align__(16) float Ksh[HWd*VP];
    __shared__ __align__(16) float ush[VP];
    __shared__ __align__(16) float vsh[VP];
    __shared__ float red[2];

    const int t = threadIdx.x;
    const int idx = blockIdx.x;
    const float* Sg = g_S + (size_t)idx*SMATS;

    float lmax = -1e30f;
    for (int i = t; i < HWd*VP; i += 64) {
        int m = i / VP, n = i - m*VP;
        float v = 0.f;
        if (n < HWd) { v = Sg[m*HWd + n]; lmax = fmaxf(lmax, v); }
        Ssh[i] = v;
    }
    #pragma unroll
    for (int o = 16; o; o >>= 1) lmax = fmaxf(lmax, __shfl_xor_sync(0xffffffffu, lmax, o));
    if ((t & 31) == 0) red[t >> 5] = lmax;
    if (t < VP) { vsh[t] = (t < HWd) ? 1.0f : 0.f; ush[t] = 0.f; }
    __syncthreads();
    const float Smax = fmaxf(red[0], red[1]);

    for (int i = t; i < HWd*VP; i += 64) {
        int m = i / VP, n = i - m*VP;
        Ksh[i] = (n < HWd) ? __expf((Ssh[i] - Smax) * INV_EPS) : 0.f;
    }
    __syncthreads();

    const bool act = t < HWd;
    float4 Kr[13], Kc[13];
    float am = 0.f, bn = 0.f;
    if (act) {
        const float4* kr4 = (const float4*)Ksh + t*13;
        #pragma unroll
        for (int j = 0; j < 13; j++) Kr[j] = kr4[j];
        #pragma unroll
        for (int j = 0; j < 12; j++)
            Kc[j] = make_float4(Ksh[(4*j)*VP + t], Ksh[(4*j+1)*VP + t],
                                Ksh[(4*j+2)*VP + t], Ksh[(4*j+3)*VP + t]);
        Kc[12] = make_float4(Ksh[48*VP + t], 0.f, 0.f, 0.f);
        am = g_ma[(size_t)idx*HWd + t];
        bn = g_mb[(size_t)idx*HWd + t];
    }
    const float4* ush4 = (const float4*)ush;
    const float4* vsh4 = (const float4*)vsh;

    #pragma unroll 1
    for (int it = 0; it < S_ITERS; it++) {
        if (act) ush[t] = __fdividef(am, dot49(Kr, vsh4));
        __syncthreads();
        if (act) vsh[t] = __fdividef(bn, dot49(Kc, ush4));
        __syncthreads();
    }

    // logits = TEMPER * sum_m u[m] * sum_n S[m,n]K[m,n]v[n]
    float part = 0.f;
    if (act) {
        const float4* sr4 = (const float4*)Ssh + t*13;
        float rsum = 0.f;
        #pragma unroll
        for (int j = 0; j < 13; j++) {
            float4 s4 = sr4[j], v4 = vsh4[j];
            rsum += s4.x*Kr[j].x*v4.x + s4.y*Kr[j].y*v4.y
                  + s4.z*Kr[j].z*v4.z + s4.w*Kr[j].w*v4.w;
        }
        part = ush[t] * rsum;
    }
    #pragma unroll
    for (int o = 16; o; o >>= 1) part += __shfl_xor_sync(0xffffffffu, part, o);
    if ((t & 31) == 0) red[t >> 5] = part;
    __syncthreads();
    if (t == 0) g_logits[idx] = TEMPER * (red[0] + red[1]);
}

// ---------------- kernel 4: cross-entropy loss ----------------
__global__ void loss_kernel(const int* __restrict__ qy, float* __restrict__ out) {
    __shared__ float red[8];
    const int t = threadIdx.x;
    float s = 0.f;
    for (int r = t; r < BQd; r += 256) {
        float l[Pd];
        #pragma unroll
        for (int k = 0; k < Pd; k++) l[k] = g_logits[r*Pd + k];
        float mx = l[0];
        #pragma unroll
        for (int k = 1; k < Pd; k++) mx = fmaxf(mx, l[k]);
        float se = 0.f;
        #pragma unroll
        for (int k = 0; k < Pd; k++) se += expf(l[k] - mx);
        float lse = mx + logf(se);
        s += lse - l[qy[r]];
    }
    #pragma unroll
    for (int o = 16; o; o >>= 1) s += __shfl_xor_sync(0xffffffffu, s, o);
    if ((t & 31) == 0) red[t >> 5] = s;
    __syncthreads();
    if (t == 0) {
        float tot = 0.f;
        #pragma unroll
        for (int i = 0; i < 8; i++) tot += red[i];
        out[0] = tot * (1.0f / BQd);
    }
}

// ---------------- launch ---------------------------------------------------
extern "C" void kernel_launch(void* const* d_in, const int* in_sizes, int n_in,
                              void* d_out, int out_size) {
    const float* sup = (const float*)d_in[0];
    const float* qry = (const float*)d_in[1];
    const int*   qy  = (const int*)d_in[3];
    float* out = (float*)d_out;

    cudaFuncSetAttribute(gaps_kernel, cudaFuncAttributeMaxDynamicSharedMemorySize, GAPS_SMEM);
    cudaFuncSetAttribute(prep_all, cudaFuncAttributeMaxDynamicSharedMemorySize, PREP_SMEM);
    cudaFuncSetAttribute(sgemm_mma_kernel, cudaFuncAttributeMaxDynamicSharedMemorySize, GEMM_SMEM);

    gaps_kernel<<<Bd*Pd + BQd, 512, GAPS_SMEM>>>(sup, qry);
    prep_all<<<Bd*Pd + BQd, 512, PREP_SMEM>>>(sup, qry);
    sgemm_mma_kernel<<<NGBLK, 256, GEMM_SMEM>>>();
    sinkhorn_kernel<<<NMAT, 64>>>();
    loss_kernel<<<1, 256>>>(qy, out);
}